// round 11
// baseline (speedup 1.0000x reference)
#include <cuda_runtime.h>
#include <cstdint>
#include <math.h>

// Problem constants
#define BB    8
#define SS    2048
#define DIN   256
#define DIMN  256
#define GAMMA 0.9865

// Block tile: 128 (M) x 64 (N), 128 threads, 4 warps, warp tile 64x32.
// Decay folded into projections: Qt_i = Q_i * g^-i * s, Kt_j = K_j * g^j * s.
// Denominator via prefix-sum: rowsum[t] = Qt_t . cumsum(Kt)[t]  (exact tril).
// ---------------------------------------------------------------------------
__device__ float g_Q[BB * SS * DIMN];
__device__ float g_K[BB * SS * DIMN];
__device__ float g_V[BB * SS * DIMN];
__device__ float g_scores[33554432];                  // BB*SS*SS = 128 MB
__device__ float g_cumK[BB * SS * DIMN];              // prefix sums of Kt
__device__ float g_segsum[BB * 64 * DIMN];            // per-segment sums / excl. prefixes
__device__ float g_denom[BB * SS];
__device__ int   g_ticket;

__device__ __forceinline__ float4 ld4(const float* p) {
    return *reinterpret_cast<const float4*>(p);
}

// tf32 split: h = rna-tf32(x), l = x - h (exact residual)
__device__ __forceinline__ void splitu(float x, uint32_t& h, uint32_t& l) {
    uint32_t u;
    asm("cvt.rna.tf32.f32 %0, %1;" : "=r"(u) : "f"(x));
    h = u;
    l = __float_as_uint(x - __uint_as_float(u));
}
__device__ __forceinline__ uint32_t to_tf32(float x) {
    uint32_t u;
    asm("cvt.rna.tf32.f32 %0, %1;" : "=r"(u) : "f"(x));
    return u;
}

__device__ __forceinline__ void mma_tf32(float* c,
                                         uint32_t a0, uint32_t a1, uint32_t a2, uint32_t a3,
                                         uint32_t b0, uint32_t b1) {
    asm volatile(
        "mma.sync.aligned.m16n8k8.row.col.f32.tf32.tf32.f32 "
        "{%0,%1,%2,%3},{%4,%5,%6,%7},{%8,%9},{%0,%1,%2,%3};\n"
        : "+f"(c[0]), "+f"(c[1]), "+f"(c[2]), "+f"(c[3])
        : "r"(a0), "r"(a1), "r"(a2), "r"(a3), "r"(b0), "r"(b1));
}

// ---------------------------------------------------------------------------
// Smem fragment layouts per 128x64x16 chunk (same as R6):
//  A: float4 aSm[16][32], B: float2 bSm[2][64][4], XOR-swizzled.
// ---------------------------------------------------------------------------

__device__ __forceinline__ void ldgA(const float* __restrict__ g, int ld, int row0, int k0,
                                     int t, float4 st[4]) {
    int ks = t >> 6, mg = (t >> 3) & 7, r = t & 7;
    const float* p = g + (size_t)(row0 + mg * 16 + r) * ld + (k0 + ks * 8);
    st[0] = ld4(p); st[1] = ld4(p + 4);
    p += (size_t)8 * ld;
    st[2] = ld4(p); st[3] = ld4(p + 4);
}
__device__ __forceinline__ void stsA(float4* aSm, int t, const float4 st[4]) {
    int ks = t >> 6, mg = (t >> 3) & 7, r = t & 7;
    int base = (ks * 8 + mg) * 32, sw = (r >> 1) & 3, r4 = r * 4;
    aSm[base + ((r4 + 0) ^ sw)] = make_float4(st[0].x, st[2].x, st[1].x, st[3].x);
    aSm[base + ((r4 + 1) ^ sw)] = make_float4(st[0].y, st[2].y, st[1].y, st[3].y);
    aSm[base + ((r4 + 2) ^ sw)] = make_float4(st[0].z, st[2].z, st[1].z, st[3].z);
    aSm[base + ((r4 + 3) ^ sw)] = make_float4(st[0].w, st[2].w, st[1].w, st[3].w);
}

__device__ __forceinline__ void ldgBD(const float* __restrict__ g, int ld, int k0, int col0,
                                      int t, float4 st[2]) {
    int kq = t & 3, cg = (t >> 2) & 15, ks = t >> 6;
    const float* p = g + (size_t)(k0 + ks * 8 + kq) * ld + col0 + cg * 4;
    st[0] = ld4(p);
    st[1] = ld4(p + (size_t)4 * ld);
}
__device__ __forceinline__ void stsBD(float2* bSm, int t, const float4 st[2]) {
    int kq = t & 3, cg = (t >> 2) & 15, ks = t >> 6;
    int base = (ks * 64 + cg * 4) * 4 + (kq ^ (cg & 3));
    bSm[base + 0]  = make_float2(st[0].x, st[1].x);
    bSm[base + 4]  = make_float2(st[0].y, st[1].y);
    bSm[base + 8]  = make_float2(st[0].z, st[1].z);
    bSm[base + 12] = make_float2(st[0].w, st[1].w);
}

__device__ __forceinline__ void ldgBT(const float* __restrict__ g, int ld, int row0, int k0,
                                      int t, float4 st[2]) {
    int cc = t & 63, ks = t >> 6;
    const float* p = g + (size_t)(row0 + cc) * ld + k0 + ks * 8;
    st[0] = ld4(p);
    st[1] = ld4(p + 4);
}
__device__ __forceinline__ void stsBT(float2* bSm, int t, const float4 st[2]) {
    int cc = t & 63, ks = t >> 6;
    int sw = (cc >> 2) & 3;
    int base = (ks * 64 + cc) * 4;
    bSm[base + (0 ^ sw)] = make_float2(st[0].x, st[1].x);
    bSm[base + (1 ^ sw)] = make_float2(st[0].y, st[1].y);
    bSm[base + (2 ^ sw)] = make_float2(st[0].z, st[1].z);
    bSm[base + (3 ^ sw)] = make_float2(st[0].w, st[1].w);
}

// ---------------------------------------------------------------------------
// Compute one k16 chunk. Warp tile 64x32. 2xTF32 split: acc += Ah*Bh + Al*Bh.
// ---------------------------------------------------------------------------
__device__ __forceinline__ void computeChunk(const float4* __restrict__ aSm,
                                             const float2* __restrict__ bSm,
                                             int mBase, int nBase, int lane,
                                             float acc[4][4][4]) {
    const int sl  = lane ^ ((lane >> 3) & 3);
    const int kqc = lane & 3;
    const int cr  = lane >> 2;
    const int mg0 = mBase >> 4;
#pragma unroll
    for (int ks = 0; ks < 2; ++ks) {
        uint32_t ah[4][4], al[4][4];
#pragma unroll
        for (int mt = 0; mt < 4; ++mt) {
            float4 fa = aSm[(ks * 8 + mg0 + mt) * 32 + sl];
            splitu(fa.x, ah[mt][0], al[mt][0]);
            splitu(fa.y, ah[mt][1], al[mt][1]);
            splitu(fa.z, ah[mt][2], al[mt][2]);
            splitu(fa.w, ah[mt][3], al[mt][3]);
        }
#pragma unroll
        for (int nt = 0; nt < 4; ++nt) {
            int cc = nBase + nt * 8 + cr;
            float2 fb = bSm[(ks * 64 + cc) * 4 + (kqc ^ ((cc >> 2) & 3))];
            uint32_t bh0 = to_tf32(fb.x);
            uint32_t bh1 = to_tf32(fb.y);
#pragma unroll
            for (int mt = 0; mt < 4; ++mt) {
                mma_tf32(acc[mt][nt], ah[mt][0], ah[mt][1], ah[mt][2], ah[mt][3], bh0, bh1);
                mma_tf32(acc[mt][nt], al[mt][0], al[mt][1], al[mt][2], al[mt][3], bh0, bh1);
            }
        }
    }
}

// ---------------------------------------------------------------------------
// Double-buffered mainloop. BT: B source is [n][k].
// ---------------------------------------------------------------------------
template <bool BT>
__device__ __forceinline__ void gemm_mainloop(
    const float* __restrict__ Ag, int lda, int arow0,
    const float* __restrict__ Bg, int ldb, int b0,
    int nChunks, int tid, int mBase, int nBase, int lane,
    float4* aSm, float2* bSm, float acc[4][4][4])
{
    float4 stA[4], stB[2];
    ldgA(Ag, lda, arow0, 0, tid, stA);
    if (BT) ldgBT(Bg, ldb, b0, 0, tid, stB);
    else    ldgBD(Bg, ldb, 0, b0, tid, stB);
    stsA(aSm, tid, stA);
    if (BT) stsBT(bSm, tid, stB);
    else    stsBD(bSm, tid, stB);

    for (int c = 0; c < nChunks; ++c) {
        __syncthreads();
        const bool more = (c + 1) < nChunks;
        if (more) {
            const int k0 = (c + 1) * 16;
            ldgA(Ag, lda, arow0, k0, tid, stA);
            if (BT) ldgBT(Bg, ldb, b0, k0, tid, stB);
            else    ldgBD(Bg, ldb, k0, b0, tid, stB);
        }
        const int cb = c & 1;
        computeChunk(aSm + cb * 512, bSm + cb * 512, mBase, nBase, lane, acc);
        if (more) {
            const int nb = (c + 1) & 1;
            stsA(aSm + nb * 512, tid, stA);
            if (BT) stsBT(bSm + nb * 512, tid, stB);
            else    stsBD(bSm + nb * 512, tid, stB);
        }
    }
}

#define DECL_SMEM() \
    __shared__ float4 aSm[1024]; \
    __shared__ float2 bSm[1024]

#define INIT_ACC(acc) \
    _Pragma("unroll") for (int _a = 0; _a < 4; ++_a) \
    _Pragma("unroll") for (int _b = 0; _b < 4; ++_b) \
    _Pragma("unroll") for (int _d = 0; _d < 4; ++_d) acc[_a][_b][_d] = 0.f

// ---------------------------------------------------------------------------
// Kernel 1: projections + decay folding.
//   z=0: Qt = (xq@Wq) * s * gamma^(-i)
//   z=1: Kt = (xk@Wk) * s * gamma^(+j)
//   z=2: V  =  xv@Wv
// grid (128, 4, 3), block 128
// ---------------------------------------------------------------------------
__global__ __launch_bounds__(128, 3)
void proj_kernel(const float* __restrict__ xq, const float* __restrict__ xk,
                 const float* __restrict__ xv,
                 const float* __restrict__ Wq, const float* __restrict__ Wk,
                 const float* __restrict__ Wv,
                 float sScale, float log2gi) {
    DECL_SMEM();
    const int tid = threadIdx.x, lane = tid & 31, warp = tid >> 5;
    const int mBase = (warp >> 1) * 64, nBase = (warp & 1) * 32;
    const int row0 = blockIdx.x * 128, col0 = blockIdx.y * 64;
    const int z = blockIdx.z;

    const float* X; const float* W; float* O;
    if (z == 0)      { X = xq; W = Wq; O = g_Q; }
    else if (z == 1) { X = xk; W = Wk; O = g_K; }
    else             { X = xv; W = Wv; O = g_V; }

    float acc[4][4][4];
    INIT_ACC(acc);
    gemm_mainloop<false>(X, DIN, row0, W, DIMN, col0, DIN / 16,
                         tid, mBase, nBase, lane, aSm, bSm, acc);

#pragma unroll
    for (int mt = 0; mt < 4; ++mt) {
        const int r = row0 + mBase + mt * 16 + (lane >> 2);
        float f0 = 1.f, f1 = 1.f;
        if (z == 0) {
            f0 = sScale * exp2f((float)(r & (SS - 1)) * log2gi);
            f1 = sScale * exp2f((float)((r + 8) & (SS - 1)) * log2gi);
        } else if (z == 1) {
            f0 = sScale * exp2f(-(float)(r & (SS - 1)) * log2gi);
            f1 = sScale * exp2f(-(float)((r + 8) & (SS - 1)) * log2gi);
        }
#pragma unroll
        for (int nt = 0; nt < 4; ++nt) {
            int cc = col0 + nBase + nt * 8 + (lane & 3) * 2;
            *reinterpret_cast<float2*>(O + (size_t)r * DIMN + cc) =
                make_float2(acc[mt][nt][0] * f0, acc[mt][nt][1] * f0);
            *reinterpret_cast<float2*>(O + (size_t)(r + 8) * DIMN + cc) =
                make_float2(acc[mt][nt][2] * f1, acc[mt][nt][3] * f1);
        }
    }
}

// ---------------------------------------------------------------------------
// Kernel 2: scores = tril(Qt Kt^T) — pure masked GEMM (no rowsum epilogue).
// grid (272, 8): L = i2*(i2+1) + j, j in 0..2*i2+1.
// ---------------------------------------------------------------------------
__global__ __launch_bounds__(128, 3)
void scores_kernel() {
    DECL_SMEM();
    const int tid = threadIdx.x, lane = tid & 31, warp = tid >> 5;
    const int mBase = (warp >> 1) * 64, nBase = (warp & 1) * 32;
    const int L = blockIdx.x, b = blockIdx.y;

    int i2 = (int)((sqrtf(4.f * (float)L + 1.f) - 1.f) * 0.5f);
    while ((i2 + 1) * (i2 + 2) <= L) ++i2;
    while (i2 * (i2 + 1) > L) --i2;
    const int j = L - i2 * (i2 + 1);     // 0 <= j <= 2*i2+1

    const float* Qp = g_Q + (size_t)b * SS * DIMN;
    const float* Kp = g_K + (size_t)b * SS * DIMN;

    float acc[4][4][4];
    INIT_ACC(acc);
    gemm_mainloop<true>(Qp, DIMN, i2 * 128, Kp, DIMN, j * 64, DIMN / 16,
                        tid, mBase, nBase, lane, aSm, bSm, acc);

    float* Sp = g_scores + (size_t)b * SS * SS;
#pragma unroll
    for (int mt = 0; mt < 4; ++mt)
#pragma unroll
        for (int h = 0; h < 2; ++h) {
            const int grow = i2 * 128 + mBase + mt * 16 + h * 8 + (lane >> 2);
#pragma unroll
            for (int nt = 0; nt < 4; ++nt) {
                const int gcol = j * 64 + nBase + nt * 8 + (lane & 3) * 2;
                const int d0 = grow - gcol;
                float v0 = (d0 >= 0)     ? acc[mt][nt][h * 2 + 0] : 0.f;
                float v1 = (d0 - 1 >= 0) ? acc[mt][nt][h * 2 + 1] : 0.f;
                *reinterpret_cast<float2*>(Sp + (size_t)grow * SS + gcol) = make_float2(v0, v1);
            }
        }
}

// ---------------------------------------------------------------------------
// Denominator pipeline: rowsum[t] = Qt_t . cumsum(Kt)[0..t]
// Segmented prefix sum over t (64 segments of 32), then per-row dot.
// All orders fixed -> deterministic.
// ---------------------------------------------------------------------------
__global__ void segsum_kernel() {          // grid (64, 8), block 256
    const int seg = blockIdx.x, b = blockIdx.y, d = threadIdx.x;
    const float* p = g_K + ((size_t)b * SS + seg * 32) * DIMN + d;
    float s = 0.f;
#pragma unroll 8
    for (int k = 0; k < 32; ++k) s += p[(size_t)k * DIMN];
    g_segsum[((size_t)b * 64 + seg) * DIMN + d] = s;
}

__global__ void segpre_kernel() {          // grid 8, block 256 (exclusive prefix)
    const int b = blockIdx.x, d = threadIdx.x;
    float run = 0.f;
    for (int s = 0; s < 64; ++s) {
        const size_t idx = ((size_t)b * 64 + s) * DIMN + d;
        const float v = g_segsum[idx];
        g_segsum[idx] = run;
        run += v;
    }
}

__global__ void cumk_kernel() {            // grid (64, 8), block 256
    const int seg = blockIdx.x, b = blockIdx.y, d = threadIdx.x;
    const float* p = g_K + ((size_t)b * SS + seg * 32) * DIMN + d;
    float* o = g_cumK + ((size_t)b * SS + seg * 32) * DIMN + d;
    float run = g_segsum[((size_t)b * 64 + seg) * DIMN + d];
#pragma unroll 8
    for (int k = 0; k < 32; ++k) {
        run += p[(size_t)k * DIMN];
        o[(size_t)k * DIMN] = run;
    }
}

__global__ void denom_kernel() {           // grid 2048, block 256 (warp per row)
    const int row = blockIdx.x * 8 + (threadIdx.x >> 5);
    const int lane = threadIdx.x & 31;
    const float* q = g_Q + (size_t)row * DIMN + lane * 8;
    const float* c = g_cumK + (size_t)row * DIMN + lane * 8;
    float s = 0.f;
#pragma unroll
    for (int i = 0; i < 8; i += 4) {
        float4 a = ld4(q + i), v = ld4(c + i);
        s += a.x * v.x + a.y * v.y + a.z * v.z + a.w * v.w;
    }
#pragma unroll
    for (int o = 16; o; o >>= 1) s += __shfl_xor_sync(0xffffffffu, s, o);
    if (lane == 0) g_denom[row] = s;
}

// ---------------------------------------------------------------------------
// Kernel 3: V[t,:] /= max(|rowsum_t|, 1); also resets the out ticket.
// ---------------------------------------------------------------------------
__global__ void vprime_kernel() {
    if (blockIdx.x == 0 && threadIdx.x == 0) g_ticket = 0;
    const int row = blockIdx.x;
    const float inv = 1.f / fmaxf(fabsf(g_denom[row]), 1.f);
    g_V[(size_t)row * DIMN + threadIdx.x] *= inv;
}

// ---------------------------------------------------------------------------
// Kernel 4: out = scores @ V'. PERSISTENT: grid 444 (=3x148) CTAs pull jobs
// from a global ticket. 512 jobs = 16 i-tiles x 4 cols x 8 batches, ordered
// big-K-first (job>>5 -> 15-i2). Each job writes a disjoint tile ->
// deterministic regardless of assignment.
// ---------------------------------------------------------------------------
__global__ __launch_bounds__(128, 3)
void out_kernel(float* __restrict__ out) {
    DECL_SMEM();
    __shared__ int sJob;
    const int tid = threadIdx.x, lane = tid & 31, warp = tid >> 5;
    const int mBase = (warp >> 1) * 64, nBase = (warp & 1) * 32;

    for (;;) {
        __syncthreads();                 // also fences smem reuse across jobs
        if (tid == 0) sJob = atomicAdd(&g_ticket, 1);
        __syncthreads();
        const int job = sJob;
        if (job >= 512) break;

        const int i2   = 15 - (job >> 5);        // big K first
        const int col0 = ((job >> 3) & 3) * 64;
        const int b    = job & 7;

        const float* Sp = g_scores + (size_t)b * SS * SS;
        const float* Vp = g_V + (size_t)b * SS * DIMN;
        float* Ob = out + (size_t)b * SS * DIMN;

        float acc[4][4][4];
        INIT_ACC(acc);

        gemm_mainloop<false>(Sp, SS, i2 * 128, Vp, DIMN, col0, (i2 + 1) * 8,
                             tid, mBase, nBase, lane, aSm, bSm, acc);

#pragma unroll
        for (int mt = 0; mt < 4; ++mt)
#pragma unroll
            for (int nt = 0; nt < 4; ++nt) {
                int r  = i2 * 128 + mBase + mt * 16 + (lane >> 2);
                int cc = col0 + nBase + nt * 8 + (lane & 3) * 2;
                *reinterpret_cast<float2*>(Ob + (size_t)r * DIMN + cc) =
                    make_float2(acc[mt][nt][0], acc[mt][nt][1]);
                *reinterpret_cast<float2*>(Ob + (size_t)(r + 8) * DIMN + cc) =
                    make_float2(acc[mt][nt][2], acc[mt][nt][3]);
            }
    }
}

// ---------------------------------------------------------------------------
// Launch
// ---------------------------------------------------------------------------
extern "C" void kernel_launch(void* const* d_in, const int* in_sizes, int n_in,
                              void* d_out, int out_size) {
    const float* xq = (const float*)d_in[0];
    const float* xk = (const float*)d_in[1];
    const float* xv = (const float*)d_in[2];
    const float* Wq = (const float*)d_in[3];
    const float* Wk = (const float*)d_in[4];
    const float* Wv = (const float*)d_in[5];
    float* out = (float*)d_out;

    // sum|D| = sum_{d=0}^{S-1} (S-d) * gamma^(-d);  D[i,j] = gamma^(j-i), i>=j
    double acc = 0.0, gp = 1.0;
    const double ginv = 1.0 / GAMMA;
    for (int d = 0; d < SS; ++d) { acc += (double)(SS - d) * gp; gp *= ginv; }
    const double scoreScale = 1.0 / (sqrt(acc) * 16.0);   // invNorm / sqrt(dim)
    const float sScale = (float)sqrt(scoreScale);         // split between Qt and Kt
    const float log2gi = (float)(-log(GAMMA) / log(2.0)); // log2(1/gamma) > 0

    proj_kernel<<<dim3(128, 4, 3), 128>>>(xq, xk, xv, Wq, Wk, Wv, sScale, log2gi);
    segsum_kernel<<<dim3(64, 8), 256>>>();
    segpre_kernel<<<8, 256>>>();
    cumk_kernel<<<dim3(64, 8), 256>>>();
    denom_kernel<<<2048, 256>>>();
    scores_kernel<<<dim3(272, 8), 128>>>();
    vprime_kernel<<<BB * SS, 256>>>();
    out_kernel<<<444, 128>>>(out);
}

// round 13
// speedup vs baseline: 1.1619x; 1.1619x over previous
#include <cuda_runtime.h>
#include <cstdint>
#include <math.h>

// Problem constants
#define BB    8
#define SS    2048
#define DIN   256
#define DIMN  256
#define GAMMA 0.9865

// proj/out: block 128x64, warp 64x32 (4 warps).  scores: block 128x128, warp 64x64.
// Decay folded into projections: Qt_i = Q_i * g^-i * s, Kt_j = K_j * g^j * s.
// ---------------------------------------------------------------------------
__device__ float g_Q[BB * SS * DIMN];
__device__ float g_K[BB * SS * DIMN];
__device__ float g_V[BB * SS * DIMN];
__device__ float g_scores[33554432];                  // BB*SS*SS = 128 MB
__device__ float g_part[BB * SS * 32];                // per-row per-128-coltile partials

__device__ __forceinline__ float4 ld4(const float* p) {
    return *reinterpret_cast<const float4*>(p);
}
__device__ __forceinline__ void splitu(float x, uint32_t& h, uint32_t& l) {
    uint32_t u;
    asm("cvt.rna.tf32.f32 %0, %1;" : "=r"(u) : "f"(x));
    h = u;
    l = __float_as_uint(x - __uint_as_float(u));
}
__device__ __forceinline__ uint32_t to_tf32(float x) {
    uint32_t u;
    asm("cvt.rna.tf32.f32 %0, %1;" : "=r"(u) : "f"(x));
    return u;
}
__device__ __forceinline__ void mma_tf32(float* c,
                                         uint32_t a0, uint32_t a1, uint32_t a2, uint32_t a3,
                                         uint32_t b0, uint32_t b1) {
    asm volatile(
        "mma.sync.aligned.m16n8k8.row.col.f32.tf32.tf32.f32 "
        "{%0,%1,%2,%3},{%4,%5,%6,%7},{%8,%9},{%0,%1,%2,%3};\n"
        : "+f"(c[0]), "+f"(c[1]), "+f"(c[2]), "+f"(c[3])
        : "r"(a0), "r"(a1), "r"(a2), "r"(a3), "r"(b0), "r"(b1));
}

// ---------------------------------------------------------------------------
// A smem (shared by all GEMMs): float4 aSm[16][32], XOR-swizzled fragments.
// ---------------------------------------------------------------------------
__device__ __forceinline__ void ldgA(const float* __restrict__ g, int ld, int row0, int k0,
                                     int t, float4 st[4]) {
    int ks = t >> 6, mg = (t >> 3) & 7, r = t & 7;
    const float* p = g + (size_t)(row0 + mg * 16 + r) * ld + (k0 + ks * 8);
    st[0] = ld4(p); st[1] = ld4(p + 4);
    p += (size_t)8 * ld;
    st[2] = ld4(p); st[3] = ld4(p + 4);
}
__device__ __forceinline__ void stsA(float4* aSm, int t, const float4 st[4]) {
    int ks = t >> 6, mg = (t >> 3) & 7, r = t & 7;
    int base = (ks * 8 + mg) * 32, sw = (r >> 1) & 3, r4 = r * 4;
    aSm[base + ((r4 + 0) ^ sw)] = make_float4(st[0].x, st[2].x, st[1].x, st[3].x);
    aSm[base + ((r4 + 1) ^ sw)] = make_float4(st[0].y, st[2].y, st[1].y, st[3].y);
    aSm[base + ((r4 + 2) ^ sw)] = make_float4(st[0].z, st[2].z, st[1].z, st[3].z);
    aSm[base + ((r4 + 3) ^ sw)] = make_float4(st[0].w, st[2].w, st[1].w, st[3].w);
}

// --------------------------- B smem, 64 cols wide ---------------------------
__device__ __forceinline__ void ldgBD(const float* __restrict__ g, int ld, int k0, int col0,
                                      int t, float4 st[2]) {
    int kq = t & 3, cg = (t >> 2) & 15, ks = t >> 6;
    const float* p = g + (size_t)(k0 + ks * 8 + kq) * ld + col0 + cg * 4;
    st[0] = ld4(p);
    st[1] = ld4(p + (size_t)4 * ld);
}
__device__ __forceinline__ void stsBD(float2* bSm, int t, const float4 st[2]) {
    int kq = t & 3, cg = (t >> 2) & 15, ks = t >> 6;
    int base = (ks * 64 + cg * 4) * 4 + (kq ^ (cg & 3));
    bSm[base + 0]  = make_float2(st[0].x, st[1].x);
    bSm[base + 4]  = make_float2(st[0].y, st[1].y);
    bSm[base + 8]  = make_float2(st[0].z, st[1].z);
    bSm[base + 12] = make_float2(st[0].w, st[1].w);
}

// --------------------------- B smem, 128 cols wide (scores) -----------------
// float2 bSm[2][128][4]: index ((ks<<7)+cc)*4 + (kq ^ ((cc>>2)&3)).
__device__ __forceinline__ void ldgBT128(const float* __restrict__ g, int ld, int row0, int k0,
                                         int t, float4 st[4]) {
#pragma unroll
    for (int uu = 0; uu < 2; ++uu) {
        int u = t + uu * 128;
        int cc = u & 127, ks = u >> 7;
        const float* p = g + (size_t)(row0 + cc) * ld + k0 + ks * 8;
        st[uu * 2 + 0] = ld4(p);
        st[uu * 2 + 1] = ld4(p + 4);
    }
}
__device__ __forceinline__ void stsBT128(float2* bSm, int t, const float4 st[4]) {
#pragma unroll
    for (int uu = 0; uu < 2; ++uu) {
        int u = t + uu * 128;
        int cc = u & 127, ks = u >> 7;
        int sw = (cc >> 2) & 3;
        int base = ((ks << 7) + cc) * 4;
        float4 lo = st[uu * 2 + 0], hi = st[uu * 2 + 1];
        bSm[base + (0 ^ sw)] = make_float2(lo.x, hi.x);
        bSm[base + (1 ^ sw)] = make_float2(lo.y, hi.y);
        bSm[base + (2 ^ sw)] = make_float2(lo.z, hi.z);
        bSm[base + (3 ^ sw)] = make_float2(lo.w, hi.w);
    }
}

// ---------------------------------------------------------------------------
// Compute chunks. 2xTF32 split: acc += Ah*Bh + Al*Bh.
// ---------------------------------------------------------------------------
__device__ __forceinline__ void computeChunk(const float4* __restrict__ aSm,
                                             const float2* __restrict__ bSm,
                                             int mBase, int nBase, int lane,
                                             float acc[4][4][4]) {
    const int sl  = lane ^ ((lane >> 3) & 3);
    const int kqc = lane & 3;
    const int cr  = lane >> 2;
    const int mg0 = mBase >> 4;
#pragma unroll
    for (int ks = 0; ks < 2; ++ks) {
        uint32_t ah[4][4], al[4][4];
#pragma unroll
        for (int mt = 0; mt < 4; ++mt) {
            float4 fa = aSm[(ks * 8 + mg0 + mt) * 32 + sl];
            splitu(fa.x, ah[mt][0], al[mt][0]);
            splitu(fa.y, ah[mt][1], al[mt][1]);
            splitu(fa.z, ah[mt][2], al[mt][2]);
            splitu(fa.w, ah[mt][3], al[mt][3]);
        }
#pragma unroll
        for (int nt = 0; nt < 4; ++nt) {
            int cc = nBase + nt * 8 + cr;
            float2 fb = bSm[(ks * 64 + cc) * 4 + (kqc ^ ((cc >> 2) & 3))];
            uint32_t bh0 = to_tf32(fb.x);
            uint32_t bh1 = to_tf32(fb.y);
#pragma unroll
            for (int mt = 0; mt < 4; ++mt) {
                mma_tf32(acc[mt][nt], ah[mt][0], ah[mt][1], ah[mt][2], ah[mt][3], bh0, bh1);
                mma_tf32(acc[mt][nt], al[mt][0], al[mt][1], al[mt][2], al[mt][3], bh0, bh1);
            }
        }
    }
}

__device__ __forceinline__ void computeChunk128(const float4* __restrict__ aSm,
                                                const float2* __restrict__ bSm,
                                                int mBase, int nBase, int lane,
                                                float acc[4][8][4]) {
    const int sl  = lane ^ ((lane >> 3) & 3);
    const int kqc = lane & 3;
    const int cr  = lane >> 2;
    const int mg0 = mBase >> 4;
#pragma unroll
    for (int ks = 0; ks < 2; ++ks) {
        uint32_t ah[4][4], al[4][4];
#pragma unroll
        for (int mt = 0; mt < 4; ++mt) {
            float4 fa = aSm[(ks * 8 + mg0 + mt) * 32 + sl];
            splitu(fa.x, ah[mt][0], al[mt][0]);
            splitu(fa.y, ah[mt][1], al[mt][1]);
            splitu(fa.z, ah[mt][2], al[mt][2]);
            splitu(fa.w, ah[mt][3], al[mt][3]);
        }
#pragma unroll
        for (int nt = 0; nt < 8; ++nt) {
            int cc = nBase + nt * 8 + cr;
            float2 fb = bSm[((ks << 7) + cc) * 4 + (kqc ^ ((cc >> 2) & 3))];
            uint32_t bh0 = to_tf32(fb.x);
            uint32_t bh1 = to_tf32(fb.y);
#pragma unroll
            for (int mt = 0; mt < 4; ++mt) {
                mma_tf32(acc[mt][nt], ah[mt][0], ah[mt][1], ah[mt][2], ah[mt][3], bh0, bh1);
                mma_tf32(acc[mt][nt], al[mt][0], al[mt][1], al[mt][2], al[mt][3], bh0, bh1);
            }
        }
    }
}

// ---------------------------------------------------------------------------
// Double-buffered 64-wide mainloop (proj, out). B direct layout only here.
// ---------------------------------------------------------------------------
__device__ __forceinline__ void gemm_mainloop64(
    const float* __restrict__ Ag, int lda, int arow0,
    const float* __restrict__ Bg, int ldb, int b0,
    int nChunks, int tid, int mBase, int nBase, int lane,
    float4* aSm, float2* bSm, float acc[4][4][4])
{
    float4 stA[4], stB[2];
    ldgA(Ag, lda, arow0, 0, tid, stA);
    ldgBD(Bg, ldb, 0, b0, tid, stB);
    stsA(aSm, tid, stA);
    stsBD(bSm, tid, stB);

    for (int c = 0; c < nChunks; ++c) {
        __syncthreads();
        const bool more = (c + 1) < nChunks;
        if (more) {
            const int k0 = (c + 1) * 16;
            ldgA(Ag, lda, arow0, k0, tid, stA);
            ldgBD(Bg, ldb, k0, b0, tid, stB);
        }
        const int cb = c & 1;
        computeChunk(aSm + cb * 512, bSm + cb * 512, mBase, nBase, lane, acc);
        if (more) {
            const int nb = (c + 1) & 1;
            stsA(aSm + nb * 512, tid, stA);
            stsBD(bSm + nb * 512, tid, stB);
        }
    }
}

#define DECL_SMEM64() \
    __shared__ float4 aSm[1024]; \
    __shared__ float2 bSm[1024]

#define INIT_ACC4(acc) \
    _Pragma("unroll") for (int _a = 0; _a < 4; ++_a) \
    _Pragma("unroll") for (int _b = 0; _b < 4; ++_b) \
    _Pragma("unroll") for (int _d = 0; _d < 4; ++_d) acc[_a][_b][_d] = 0.f

#define INIT_ACC8(acc) \
    _Pragma("unroll") for (int _a = 0; _a < 4; ++_a) \
    _Pragma("unroll") for (int _b = 0; _b < 8; ++_b) \
    _Pragma("unroll") for (int _d = 0; _d < 4; ++_d) acc[_a][_b][_d] = 0.f

// ---------------------------------------------------------------------------
// Kernel 1: projections + decay folding.
//   z=0: Qt = (xq@Wq) * s * gamma^(-i);  z=1: Kt = (xk@Wk) * s * gamma^(+j);
//   z=2: V = xv@Wv.   grid (128, 4, 3), block 128.
// ---------------------------------------------------------------------------
__global__ __launch_bounds__(128, 3)
void proj_kernel(const float* __restrict__ xq, const float* __restrict__ xk,
                 const float* __restrict__ xv,
                 const float* __restrict__ Wq, const float* __restrict__ Wk,
                 const float* __restrict__ Wv,
                 float sScale, float log2gi) {
    DECL_SMEM64();
    const int tid = threadIdx.x, lane = tid & 31, warp = tid >> 5;
    const int mBase = (warp >> 1) * 64, nBase = (warp & 1) * 32;
    const int row0 = blockIdx.x * 128, col0 = blockIdx.y * 64;
    const int z = blockIdx.z;

    const float* X; const float* W; float* O;
    if (z == 0)      { X = xq; W = Wq; O = g_Q; }
    else if (z == 1) { X = xk; W = Wk; O = g_K; }
    else             { X = xv; W = Wv; O = g_V; }

    float acc[4][4][4];
    INIT_ACC4(acc);
    gemm_mainloop64(X, DIN, row0, W, DIMN, col0, DIN / 16,
                    tid, mBase, nBase, lane, aSm, bSm, acc);

#pragma unroll
    for (int mt = 0; mt < 4; ++mt) {
        const int r = row0 + mBase + mt * 16 + (lane >> 2);
        float f0 = 1.f, f1 = 1.f;
        if (z == 0) {
            f0 = sScale * exp2f((float)(r & (SS - 1)) * log2gi);
            f1 = sScale * exp2f((float)((r + 8) & (SS - 1)) * log2gi);
        } else if (z == 1) {
            f0 = sScale * exp2f(-(float)(r & (SS - 1)) * log2gi);
            f1 = sScale * exp2f(-(float)((r + 8) & (SS - 1)) * log2gi);
        }
#pragma unroll
        for (int nt = 0; nt < 4; ++nt) {
            int cc = col0 + nBase + nt * 8 + (lane & 3) * 2;
            *reinterpret_cast<float2*>(O + (size_t)r * DIMN + cc) =
                make_float2(acc[mt][nt][0] * f0, acc[mt][nt][1] * f0);
            *reinterpret_cast<float2*>(O + (size_t)(r + 8) * DIMN + cc) =
                make_float2(acc[mt][nt][2] * f1, acc[mt][nt][3] * f1);
        }
    }
}

// ---------------------------------------------------------------------------
// Kernel 2: scores = tril(Qt Kt^T), 128x128 tiles, warp tile 64x64.
// grid (136, 8): L = i2*(i2+1)/2 + j, j <= i2. Emits per-row partial sums.
// ---------------------------------------------------------------------------
__global__ __launch_bounds__(128)
void scores_kernel() {
    __shared__ float4 aSm[1024];     // 2 x 512 (16 KB)
    __shared__ float2 bSm[2048];     // 2 x 1024 (16 KB)
    __shared__ float rowAcc[128];

    const int tid = threadIdx.x, lane = tid & 31, warp = tid >> 5;
    const int mBase = (warp >> 1) * 64, nBase = (warp & 1) * 64;
    const int L = blockIdx.x, b = blockIdx.y;

    int i2 = (int)((sqrtf(8.f * (float)L + 1.f) - 1.f) * 0.5f);
    while ((i2 + 1) * (i2 + 2) / 2 <= L) ++i2;
    while (i2 * (i2 + 1) / 2 > L) --i2;
    const int j = L - i2 * (i2 + 1) / 2;   // j <= i2

    const float* Qp = g_Q + (size_t)b * SS * DIMN;
    const float* Kp = g_K + (size_t)b * SS * DIMN;

    rowAcc[tid] = 0.f;

    float acc[4][8][4];
    INIT_ACC8(acc);

    // mainloop: 16 chunks of k16, double-buffered
    {
        float4 stA[4], stB[4];
        ldgA(Qp, DIMN, i2 * 128, 0, tid, stA);
        ldgBT128(Kp, DIMN, j * 128, 0, tid, stB);
        stsA(aSm, tid, stA);
        stsBT128(bSm, tid, stB);
        for (int c = 0; c < 16; ++c) {
            __syncthreads();
            const bool more = (c + 1) < 16;
            if (more) {
                const int k0 = (c + 1) * 16;
                ldgA(Qp, DIMN, i2 * 128, k0, tid, stA);
                ldgBT128(Kp, DIMN, j * 128, k0, tid, stB);
            }
            const int cb = c & 1;
            computeChunk128(aSm + cb * 512, bSm + cb * 1024, mBase, nBase, lane, acc);
            if (more) {
                const int nb = (c + 1) & 1;
                stsA(aSm + nb * 512, tid, stA);
                stsBT128(bSm + nb * 1024, tid, stB);
            }
        }
    }

    float* Sp = g_scores + (size_t)b * SS * SS;
#pragma unroll
    for (int mt = 0; mt < 4; ++mt)
#pragma unroll
        for (int h = 0; h < 2; ++h) {
            const int lr   = mBase + mt * 16 + h * 8 + (lane >> 2);
            const int grow = i2 * 128 + lr;
            float rsum = 0.f;
#pragma unroll
            for (int nt = 0; nt < 8; ++nt) {
                const int gcol = j * 128 + nBase + nt * 8 + (lane & 3) * 2;
                const int d0 = grow - gcol;
                float v0 = (d0 >= 0)     ? acc[mt][nt][h * 2 + 0] : 0.f;
                float v1 = (d0 - 1 >= 0) ? acc[mt][nt][h * 2 + 1] : 0.f;
                *reinterpret_cast<float2*>(Sp + (size_t)grow * SS + gcol) = make_float2(v0, v1);
                rsum += v0 + v1;
            }
            rsum += __shfl_xor_sync(0xffffffffu, rsum, 1);
            rsum += __shfl_xor_sync(0xffffffffu, rsum, 2);
            if ((lane & 3) == 0) atomicAdd(&rowAcc[lr], rsum);  // 2 commutative adds/slot
        }
    __syncthreads();
    g_part[((size_t)b * SS + i2 * 128 + tid) * 32 + j] = rowAcc[tid];
}

// ---------------------------------------------------------------------------
// Kernel 3: V[t,:] /= max(|rowsum_t|, 1)  (sequential, deterministic)
// ---------------------------------------------------------------------------
__global__ void vprime_kernel() {
    const int row = blockIdx.x;
    const int s   = row & (SS - 1);
    __shared__ float inv;
    if (threadIdx.x == 0) {
        float acc = 0.f;
        const int jm = s >> 7;            // 128-wide col tiles now
        const float* p = g_part + (size_t)row * 32;
        for (int jt = 0; jt <= jm; ++jt) acc += p[jt];
        inv = 1.f / fmaxf(fabsf(acc), 1.f);
    }
    __syncthreads();
    g_V[(size_t)row * DIMN + threadIdx.x] *= inv;
}

// ---------------------------------------------------------------------------
// Kernel 4: out = scores @ V'. Uniform-work pairing: block x handles row
// tiles i2 = x and 15 - x. grid (8, 4, 8) = 256 identical blocks.
// ---------------------------------------------------------------------------
__global__ __launch_bounds__(128, 3)
void out_kernel(float* __restrict__ out) {
    DECL_SMEM64();
    const int tid = threadIdx.x, lane = tid & 31, warp = tid >> 5;
    const int mBase = (warp >> 1) * 64, nBase = (warp & 1) * 32;
    const int col0 = blockIdx.y * 64;
    const int b = blockIdx.z;

    const float* Sp = g_scores + (size_t)b * SS * SS;
    const float* Vp = g_V + (size_t)b * SS * DIMN;
    float* Ob = out + (size_t)b * SS * DIMN;

#pragma unroll 1
    for (int half = 0; half < 2; ++half) {
        const int i2 = half ? (15 - (int)blockIdx.x) : (int)blockIdx.x;

        __syncthreads();   // protect smem reuse across the two mainloops

        float acc[4][4][4];
        INIT_ACC4(acc);

        gemm_mainloop64(Sp, SS, i2 * 128, Vp, DIMN, col0, (i2 + 1) * 8,
                        tid, mBase, nBase, lane, aSm, bSm, acc);

#pragma unroll
        for (int mt = 0; mt < 4; ++mt)
#pragma unroll
            for (int nt = 0; nt < 4; ++nt) {
                int r  = i2 * 128 + mBase + mt * 16 + (lane >> 2);
                int cc = col0 + nBase + nt * 8 + (lane & 3) * 2;
                *reinterpret_cast<float2*>(Ob + (size_t)r * DIMN + cc) =
                    make_float2(acc[mt][nt][0], acc[mt][nt][1]);
                *reinterpret_cast<float2*>(Ob + (size_t)(r + 8) * DIMN + cc) =
                    make_float2(acc[mt][nt][2], acc[mt][nt][3]);
            }
    }
}

// ---------------------------------------------------------------------------
// Launch
// ---------------------------------------------------------------------------
extern "C" void kernel_launch(void* const* d_in, const int* in_sizes, int n_in,
                              void* d_out, int out_size) {
    const float* xq = (const float*)d_in[0];
    const float* xk = (const float*)d_in[1];
    const float* xv = (const float*)d_in[2];
    const float* Wq = (const float*)d_in[3];
    const float* Wk = (const float*)d_in[4];
    const float* Wv = (const float*)d_in[5];
    float* out = (float*)d_out;

    // sum|D| = sum_{d=0}^{S-1} (S-d) * gamma^(-d);  D[i,j] = gamma^(j-i), i>=j
    double acc = 0.0, gp = 1.0;
    const double ginv = 1.0 / GAMMA;
    for (int d = 0; d < SS; ++d) { acc += (double)(SS - d) * gp; gp *= ginv; }
    const double scoreScale = 1.0 / (sqrt(acc) * 16.0);   // invNorm / sqrt(dim)
    const float sScale = (float)sqrt(scoreScale);         // split between Qt and Kt
    const float log2gi = (float)(-log(GAMMA) / log(2.0)); // log2(1/gamma) > 0

    proj_kernel<<<dim3(128, 4, 3), 128>>>(xq, xk, xv, Wq, Wk, Wv, sScale, log2gi);
    scores_kernel<<<dim3(136, 8), 128>>>();
    vprime_kernel<<<BB * SS, 256>>>();
    out_kernel<<<dim3(8, 4, 8), 128>>>(out);
}

// round 14
// speedup vs baseline: 1.2377x; 1.0653x over previous
#include <cuda_runtime.h>
#include <cstdint>
#include <math.h>

// Problem constants
#define BB    8
#define SS    2048
#define DIN   256
#define DIMN  256
#define GAMMA 0.9865

// proj: block 128x64 (warp 64x32). scores/out: block 128x128 (warp 64x64).
// out uses split-K x2 into partial buffers + combine (deterministic).
// Decay folded into projections: Qt_i = Q_i * g^-i * s, Kt_j = K_j * g^j * s.
// ---------------------------------------------------------------------------
__device__ float g_Q[BB * SS * DIMN];
__device__ float g_K[BB * SS * DIMN];
__device__ float g_V[BB * SS * DIMN];
__device__ float g_scores[33554432];                  // BB*SS*SS = 128 MB
__device__ float g_part[BB * SS * 32];                // per-row per-128-coltile partials
__device__ float g_outPart[2][BB * SS * DIMN];        // split-K partials (2 x 16 MB)

__device__ __forceinline__ float4 ld4(const float* p) {
    return *reinterpret_cast<const float4*>(p);
}
__device__ __forceinline__ void splitu(float x, uint32_t& h, uint32_t& l) {
    uint32_t u;
    asm("cvt.rna.tf32.f32 %0, %1;" : "=r"(u) : "f"(x));
    h = u;
    l = __float_as_uint(x - __uint_as_float(u));
}
__device__ __forceinline__ uint32_t to_tf32(float x) {
    uint32_t u;
    asm("cvt.rna.tf32.f32 %0, %1;" : "=r"(u) : "f"(x));
    return u;
}
__device__ __forceinline__ void mma_tf32(float* c,
                                         uint32_t a0, uint32_t a1, uint32_t a2, uint32_t a3,
                                         uint32_t b0, uint32_t b1) {
    asm volatile(
        "mma.sync.aligned.m16n8k8.row.col.f32.tf32.tf32.f32 "
        "{%0,%1,%2,%3},{%4,%5,%6,%7},{%8,%9},{%0,%1,%2,%3};\n"
        : "+f"(c[0]), "+f"(c[1]), "+f"(c[2]), "+f"(c[3])
        : "r"(a0), "r"(a1), "r"(a2), "r"(a3), "r"(b0), "r"(b1));
}

// ---------------------------------------------------------------------------
// A smem: float4 aSm[16][32], XOR-swizzled fragments (all GEMMs).
// ---------------------------------------------------------------------------
__device__ __forceinline__ void ldgA(const float* __restrict__ g, int ld, int row0, int k0,
                                     int t, float4 st[4]) {
    int ks = t >> 6, mg = (t >> 3) & 7, r = t & 7;
    const float* p = g + (size_t)(row0 + mg * 16 + r) * ld + (k0 + ks * 8);
    st[0] = ld4(p); st[1] = ld4(p + 4);
    p += (size_t)8 * ld;
    st[2] = ld4(p); st[3] = ld4(p + 4);
}
__device__ __forceinline__ void stsA(float4* aSm, int t, const float4 st[4]) {
    int ks = t >> 6, mg = (t >> 3) & 7, r = t & 7;
    int base = (ks * 8 + mg) * 32, sw = (r >> 1) & 3, r4 = r * 4;
    aSm[base + ((r4 + 0) ^ sw)] = make_float4(st[0].x, st[2].x, st[1].x, st[3].x);
    aSm[base + ((r4 + 1) ^ sw)] = make_float4(st[0].y, st[2].y, st[1].y, st[3].y);
    aSm[base + ((r4 + 2) ^ sw)] = make_float4(st[0].z, st[2].z, st[1].z, st[3].z);
    aSm[base + ((r4 + 3) ^ sw)] = make_float4(st[0].w, st[2].w, st[1].w, st[3].w);
}

// --------------------------- B smem, 64 cols (proj) -------------------------
__device__ __forceinline__ void ldgBD(const float* __restrict__ g, int ld, int k0, int col0,
                                      int t, float4 st[2]) {
    int kq = t & 3, cg = (t >> 2) & 15, ks = t >> 6;
    const float* p = g + (size_t)(k0 + ks * 8 + kq) * ld + col0 + cg * 4;
    st[0] = ld4(p);
    st[1] = ld4(p + (size_t)4 * ld);
}
__device__ __forceinline__ void stsBD(float2* bSm, int t, const float4 st[2]) {
    int kq = t & 3, cg = (t >> 2) & 15, ks = t >> 6;
    int base = (ks * 64 + cg * 4) * 4 + (kq ^ (cg & 3));
    bSm[base + 0]  = make_float2(st[0].x, st[1].x);
    bSm[base + 4]  = make_float2(st[0].y, st[1].y);
    bSm[base + 8]  = make_float2(st[0].z, st[1].z);
    bSm[base + 12] = make_float2(st[0].w, st[1].w);
}

// --------------------------- B smem, 128 cols -------------------------------
// float2 bSm[2][128][4]: index ((ks<<7)+cc)*4 + (kq ^ ((cc>>2)&3)).
// Transposed source [n][k] (K matrix, scores):
__device__ __forceinline__ void ldgBT128(const float* __restrict__ g, int ld, int row0, int k0,
                                         int t, float4 st[4]) {
#pragma unroll
    for (int uu = 0; uu < 2; ++uu) {
        int u = t + uu * 128;
        int cc = u & 127, ks = u >> 7;
        const float* p = g + (size_t)(row0 + cc) * ld + k0 + ks * 8;
        st[uu * 2 + 0] = ld4(p);
        st[uu * 2 + 1] = ld4(p + 4);
    }
}
__device__ __forceinline__ void stsBT128(float2* bSm, int t, const float4 st[4]) {
#pragma unroll
    for (int uu = 0; uu < 2; ++uu) {
        int u = t + uu * 128;
        int cc = u & 127, ks = u >> 7;
        int sw = (cc >> 2) & 3;
        int base = ((ks << 7) + cc) * 4;
        float4 lo = st[uu * 2 + 0], hi = st[uu * 2 + 1];
        bSm[base + (0 ^ sw)] = make_float2(lo.x, hi.x);
        bSm[base + (1 ^ sw)] = make_float2(lo.y, hi.y);
        bSm[base + (2 ^ sw)] = make_float2(lo.z, hi.z);
        bSm[base + (3 ^ sw)] = make_float2(lo.w, hi.w);
    }
}
// Direct source [k][n] (V matrix, out):
__device__ __forceinline__ void ldgBD128(const float* __restrict__ g, int ld, int k0, int col0,
                                         int t, float4 st[4]) {
#pragma unroll
    for (int uu = 0; uu < 2; ++uu) {
        int u = t + uu * 128;
        int kq = u & 3, cg = (u >> 2) & 31, ks = u >> 7;
        const float* p = g + (size_t)(k0 + ks * 8 + kq) * ld + col0 + cg * 4;
        st[uu * 2 + 0] = ld4(p);
        st[uu * 2 + 1] = ld4(p + (size_t)4 * ld);
    }
}
__device__ __forceinline__ void stsBD128(float2* bSm, int t, const float4 st[4]) {
#pragma unroll
    for (int uu = 0; uu < 2; ++uu) {
        int u = t + uu * 128;
        int kq = u & 3, cg = (u >> 2) & 31, ks = u >> 7;
        int base = ((ks << 7) + cg * 4) * 4 + (kq ^ (cg & 3));
        float4 lo = st[uu * 2 + 0], hi = st[uu * 2 + 1];
        bSm[base + 0]  = make_float2(lo.x, hi.x);
        bSm[base + 4]  = make_float2(lo.y, hi.y);
        bSm[base + 8]  = make_float2(lo.z, hi.z);
        bSm[base + 12] = make_float2(lo.w, hi.w);
    }
}

// ---------------------------------------------------------------------------
// Compute chunks. 2xTF32 split: acc += Ah*Bh + Al*Bh.
// ---------------------------------------------------------------------------
__device__ __forceinline__ void computeChunk(const float4* __restrict__ aSm,
                                             const float2* __restrict__ bSm,
                                             int mBase, int nBase, int lane,
                                             float acc[4][4][4]) {
    const int sl  = lane ^ ((lane >> 3) & 3);
    const int kqc = lane & 3;
    const int cr  = lane >> 2;
    const int mg0 = mBase >> 4;
#pragma unroll
    for (int ks = 0; ks < 2; ++ks) {
        uint32_t ah[4][4], al[4][4];
#pragma unroll
        for (int mt = 0; mt < 4; ++mt) {
            float4 fa = aSm[(ks * 8 + mg0 + mt) * 32 + sl];
            splitu(fa.x, ah[mt][0], al[mt][0]);
            splitu(fa.y, ah[mt][1], al[mt][1]);
            splitu(fa.z, ah[mt][2], al[mt][2]);
            splitu(fa.w, ah[mt][3], al[mt][3]);
        }
#pragma unroll
        for (int nt = 0; nt < 4; ++nt) {
            int cc = nBase + nt * 8 + cr;
            float2 fb = bSm[(ks * 64 + cc) * 4 + (kqc ^ ((cc >> 2) & 3))];
            uint32_t bh0 = to_tf32(fb.x);
            uint32_t bh1 = to_tf32(fb.y);
#pragma unroll
            for (int mt = 0; mt < 4; ++mt) {
                mma_tf32(acc[mt][nt], ah[mt][0], ah[mt][1], ah[mt][2], ah[mt][3], bh0, bh1);
                mma_tf32(acc[mt][nt], al[mt][0], al[mt][1], al[mt][2], al[mt][3], bh0, bh1);
            }
        }
    }
}

__device__ __forceinline__ void computeChunk128(const float4* __restrict__ aSm,
                                                const float2* __restrict__ bSm,
                                                int mBase, int nBase, int lane,
                                                float acc[4][8][4]) {
    const int sl  = lane ^ ((lane >> 3) & 3);
    const int kqc = lane & 3;
    const int cr  = lane >> 2;
    const int mg0 = mBase >> 4;
#pragma unroll
    for (int ks = 0; ks < 2; ++ks) {
        uint32_t ah[4][4], al[4][4];
#pragma unroll
        for (int mt = 0; mt < 4; ++mt) {
            float4 fa = aSm[(ks * 8 + mg0 + mt) * 32 + sl];
            splitu(fa.x, ah[mt][0], al[mt][0]);
            splitu(fa.y, ah[mt][1], al[mt][1]);
            splitu(fa.z, ah[mt][2], al[mt][2]);
            splitu(fa.w, ah[mt][3], al[mt][3]);
        }
#pragma unroll
        for (int nt = 0; nt < 8; ++nt) {
            int cc = nBase + nt * 8 + cr;
            float2 fb = bSm[((ks << 7) + cc) * 4 + (kqc ^ ((cc >> 2) & 3))];
            uint32_t bh0 = to_tf32(fb.x);
            uint32_t bh1 = to_tf32(fb.y);
#pragma unroll
            for (int mt = 0; mt < 4; ++mt) {
                mma_tf32(acc[mt][nt], ah[mt][0], ah[mt][1], ah[mt][2], ah[mt][3], bh0, bh1);
                mma_tf32(acc[mt][nt], al[mt][0], al[mt][1], al[mt][2], al[mt][3], bh0, bh1);
            }
        }
    }
}

// ---------------------------------------------------------------------------
// Double-buffered 64-wide mainloop (proj).
// ---------------------------------------------------------------------------
__device__ __forceinline__ void gemm_mainloop64(
    const float* __restrict__ Ag, int lda, int arow0,
    const float* __restrict__ Bg, int ldb, int b0,
    int nChunks, int tid, int mBase, int nBase, int lane,
    float4* aSm, float2* bSm, float acc[4][4][4])
{
    float4 stA[4], stB[2];
    ldgA(Ag, lda, arow0, 0, tid, stA);
    ldgBD(Bg, ldb, 0, b0, tid, stB);
    stsA(aSm, tid, stA);
    stsBD(bSm, tid, stB);

    for (int c = 0; c < nChunks; ++c) {
        __syncthreads();
        const bool more = (c + 1) < nChunks;
        if (more) {
            const int k0 = (c + 1) * 16;
            ldgA(Ag, lda, arow0, k0, tid, stA);
            ldgBD(Bg, ldb, k0, b0, tid, stB);
        }
        const int cb = c & 1;
        computeChunk(aSm + cb * 512, bSm + cb * 512, mBase, nBase, lane, acc);
        if (more) {
            const int nb = (c + 1) & 1;
            stsA(aSm + nb * 512, tid, stA);
            stsBD(bSm + nb * 512, tid, stB);
        }
    }
}

#define INIT_ACC4(acc) \
    _Pragma("unroll") for (int _a = 0; _a < 4; ++_a) \
    _Pragma("unroll") for (int _b = 0; _b < 4; ++_b) \
    _Pragma("unroll") for (int _d = 0; _d < 4; ++_d) acc[_a][_b][_d] = 0.f

#define INIT_ACC8(acc) \
    _Pragma("unroll") for (int _a = 0; _a < 4; ++_a) \
    _Pragma("unroll") for (int _b = 0; _b < 8; ++_b) \
    _Pragma("unroll") for (int _d = 0; _d < 4; ++_d) acc[_a][_b][_d] = 0.f

// ---------------------------------------------------------------------------
// Kernel 1: projections + decay folding. grid (128, 4, 3), block 128.
// ---------------------------------------------------------------------------
__global__ __launch_bounds__(128, 3)
void proj_kernel(const float* __restrict__ xq, const float* __restrict__ xk,
                 const float* __restrict__ xv,
                 const float* __restrict__ Wq, const float* __restrict__ Wk,
                 const float* __restrict__ Wv,
                 float sScale, float log2gi) {
    __shared__ float4 aSm[1024];
    __shared__ float2 bSm[1024];
    const int tid = threadIdx.x, lane = tid & 31, warp = tid >> 5;
    const int mBase = (warp >> 1) * 64, nBase = (warp & 1) * 32;
    const int row0 = blockIdx.x * 128, col0 = blockIdx.y * 64;
    const int z = blockIdx.z;

    const float* X; const float* W; float* O;
    if (z == 0)      { X = xq; W = Wq; O = g_Q; }
    else if (z == 1) { X = xk; W = Wk; O = g_K; }
    else             { X = xv; W = Wv; O = g_V; }

    float acc[4][4][4];
    INIT_ACC4(acc);
    gemm_mainloop64(X, DIN, row0, W, DIMN, col0, DIN / 16,
                    tid, mBase, nBase, lane, aSm, bSm, acc);

#pragma unroll
    for (int mt = 0; mt < 4; ++mt) {
        const int r = row0 + mBase + mt * 16 + (lane >> 2);
        float f0 = 1.f, f1 = 1.f;
        if (z == 0) {
            f0 = sScale * exp2f((float)(r & (SS - 1)) * log2gi);
            f1 = sScale * exp2f((float)((r + 8) & (SS - 1)) * log2gi);
        } else if (z == 1) {
            f0 = sScale * exp2f(-(float)(r & (SS - 1)) * log2gi);
            f1 = sScale * exp2f(-(float)((r + 8) & (SS - 1)) * log2gi);
        }
#pragma unroll
        for (int nt = 0; nt < 4; ++nt) {
            int cc = col0 + nBase + nt * 8 + (lane & 3) * 2;
            *reinterpret_cast<float2*>(O + (size_t)r * DIMN + cc) =
                make_float2(acc[mt][nt][0] * f0, acc[mt][nt][1] * f0);
            *reinterpret_cast<float2*>(O + (size_t)(r + 8) * DIMN + cc) =
                make_float2(acc[mt][nt][2] * f1, acc[mt][nt][3] * f1);
        }
    }
}

// ---------------------------------------------------------------------------
// Kernel 2: scores = tril(Qt Kt^T), 128x128 tiles, warp tile 64x64.
// grid (136, 8). Emits per-row partial sums.
// ---------------------------------------------------------------------------
__global__ __launch_bounds__(128)
void scores_kernel() {
    __shared__ float4 aSm[1024];     // 2 x 512 (16 KB)
    __shared__ float2 bSm[2048];     // 2 x 1024 (16 KB)
    __shared__ float rowAcc[128];

    const int tid = threadIdx.x, lane = tid & 31, warp = tid >> 5;
    const int mBase = (warp >> 1) * 64, nBase = (warp & 1) * 64;
    const int L = blockIdx.x, b = blockIdx.y;

    int i2 = (int)((sqrtf(8.f * (float)L + 1.f) - 1.f) * 0.5f);
    while ((i2 + 1) * (i2 + 2) / 2 <= L) ++i2;
    while (i2 * (i2 + 1) / 2 > L) --i2;
    const int j = L - i2 * (i2 + 1) / 2;   // j <= i2

    const float* Qp = g_Q + (size_t)b * SS * DIMN;
    const float* Kp = g_K + (size_t)b * SS * DIMN;

    rowAcc[tid] = 0.f;

    float acc[4][8][4];
    INIT_ACC8(acc);

    {
        float4 stA[4], stB[4];
        ldgA(Qp, DIMN, i2 * 128, 0, tid, stA);
        ldgBT128(Kp, DIMN, j * 128, 0, tid, stB);
        stsA(aSm, tid, stA);
        stsBT128(bSm, tid, stB);
        for (int c = 0; c < 16; ++c) {
            __syncthreads();
            const bool more = (c + 1) < 16;
            if (more) {
                const int k0 = (c + 1) * 16;
                ldgA(Qp, DIMN, i2 * 128, k0, tid, stA);
                ldgBT128(Kp, DIMN, j * 128, k0, tid, stB);
            }
            const int cb = c & 1;
            computeChunk128(aSm + cb * 512, bSm + cb * 1024, mBase, nBase, lane, acc);
            if (more) {
                const int nb = (c + 1) & 1;
                stsA(aSm + nb * 512, tid, stA);
                stsBT128(bSm + nb * 1024, tid, stB);
            }
        }
    }

    float* Sp = g_scores + (size_t)b * SS * SS;
#pragma unroll
    for (int mt = 0; mt < 4; ++mt)
#pragma unroll
        for (int h = 0; h < 2; ++h) {
            const int lr   = mBase + mt * 16 + h * 8 + (lane >> 2);
            const int grow = i2 * 128 + lr;
            float rsum = 0.f;
#pragma unroll
            for (int nt = 0; nt < 8; ++nt) {
                const int gcol = j * 128 + nBase + nt * 8 + (lane & 3) * 2;
                const int d0 = grow - gcol;
                float v0 = (d0 >= 0)     ? acc[mt][nt][h * 2 + 0] : 0.f;
                float v1 = (d0 - 1 >= 0) ? acc[mt][nt][h * 2 + 1] : 0.f;
                *reinterpret_cast<float2*>(Sp + (size_t)grow * SS + gcol) = make_float2(v0, v1);
                rsum += v0 + v1;
            }
            rsum += __shfl_xor_sync(0xffffffffu, rsum, 1);
            rsum += __shfl_xor_sync(0xffffffffu, rsum, 2);
            if ((lane & 3) == 0) atomicAdd(&rowAcc[lr], rsum);  // 2 commutative adds/slot
        }
    __syncthreads();
    g_part[((size_t)b * SS + i2 * 128 + tid) * 32 + j] = rowAcc[tid];
}

// ---------------------------------------------------------------------------
// Kernel 3: V[t,:] /= max(|rowsum_t|, 1)  (sequential, deterministic)
// ---------------------------------------------------------------------------
__global__ void vprime_kernel() {
    const int row = blockIdx.x;
    const int s   = row & (SS - 1);
    __shared__ float inv;
    if (threadIdx.x == 0) {
        float acc = 0.f;
        const int jm = s >> 7;
        const float* p = g_part + (size_t)row * 32;
        for (int jt = 0; jt <= jm; ++jt) acc += p[jt];
        inv = 1.f / fmaxf(fabsf(acc), 1.f);
    }
    __syncthreads();
    g_V[(size_t)row * DIMN + threadIdx.x] *= inv;
}

// ---------------------------------------------------------------------------
// Kernel 4: out partials. Block 128x128, warp 64x64, split-K x2.
// grid (8, 4, 8): x pairs i-tiles (x, 15-x); y = colhalf + 2*khalf; z = b.
// Each block: 68 chunks total (uniform). Writes g_outPart[khalf].
// ---------------------------------------------------------------------------
__global__ __launch_bounds__(128)
void out_kernel() {
    __shared__ float4 aSm[1024];     // 2 x 512 (16 KB)
    __shared__ float2 bSm[2048];     // 2 x 1024 (16 KB)

    const int tid = threadIdx.x, lane = tid & 31, warp = tid >> 5;
    const int mBase = (warp >> 1) * 64, nBase = (warp & 1) * 64;
    const int colhalf = blockIdx.y & 1;
    const int khalf   = blockIdx.y >> 1;
    const int col0 = colhalf * 128;
    const int b = blockIdx.z;

    const float* Sp = g_scores + (size_t)b * SS * SS;
    const float* Vp = g_V + (size_t)b * SS * DIMN;
    float* Op = g_outPart[khalf] + (size_t)b * SS * DIMN;

#pragma unroll 1
    for (int half = 0; half < 2; ++half) {
        const int i2 = half ? (15 - (int)blockIdx.x) : (int)blockIdx.x;
        const int kstart  = khalf * (i2 + 1) * 64;     // this half's K start
        const int nChunks = (i2 + 1) * 4;              // (i2+1)*64 / 16

        __syncthreads();   // protect smem reuse across the two mainloops

        float acc[4][8][4];
        INIT_ACC8(acc);

        {
            float4 stA[4], stB[4];
            ldgA(Sp, SS, i2 * 128, kstart, tid, stA);
            ldgBD128(Vp, DIMN, kstart, col0, tid, stB);
            stsA(aSm, tid, stA);
            stsBD128(bSm, tid, stB);
            for (int c = 0; c < nChunks; ++c) {
                __syncthreads();
                const bool more = (c + 1) < nChunks;
                if (more) {
                    const int k0 = kstart + (c + 1) * 16;
                    ldgA(Sp, SS, i2 * 128, k0, tid, stA);
                    ldgBD128(Vp, DIMN, k0, col0, tid, stB);
                }
                const int cb = c & 1;
                computeChunk128(aSm + cb * 512, bSm + cb * 1024, mBase, nBase, lane, acc);
                if (more) {
                    const int nb = (c + 1) & 1;
                    stsA(aSm + nb * 512, tid, stA);
                    stsBD128(bSm + nb * 1024, tid, stB);
                }
            }
        }

#pragma unroll
        for (int mt = 0; mt < 4; ++mt)
#pragma unroll
            for (int nt = 0; nt < 8; ++nt) {
                int r  = i2 * 128 + mBase + mt * 16 + (lane >> 2);
                int cc = col0 + nBase + nt * 8 + (lane & 3) * 2;
                *reinterpret_cast<float2*>(Op + (size_t)r * DIMN + cc) =
                    make_float2(acc[mt][nt][0], acc[mt][nt][1]);
                *reinterpret_cast<float2*>(Op + (size_t)(r + 8) * DIMN + cc) =
                    make_float2(acc[mt][nt][2], acc[mt][nt][3]);
            }
    }
}

// ---------------------------------------------------------------------------
// Kernel 5: combine split-K partials: out = p0 + p1 (deterministic).
// grid 4096, block 256, float4 per thread.
// ---------------------------------------------------------------------------
__global__ void combine_kernel(float* __restrict__ out) {
    const size_t i = ((size_t)blockIdx.x * 256 + threadIdx.x) * 4;
    float4 a = ld4(&g_outPart[0][i]);
    float4 c = ld4(&g_outPart[1][i]);
    *reinterpret_cast<float4*>(out + i) =
        make_float4(a.x + c.x, a.y + c.y, a.z + c.z, a.w + c.w);
}

// ---------------------------------------------------------------------------
// Launch
// ---------------------------------------------------------------------------
extern "C" void kernel_launch(void* const* d_in, const int* in_sizes, int n_in,
                              void* d_out, int out_size) {
    const float* xq = (const float*)d_in[0];
    const float* xk = (const float*)d_in[1];
    const float* xv = (const float*)d_in[2];
    const float* Wq = (const float*)d_in[3];
    const float* Wk = (const float*)d_in[4];
    const float* Wv = (const float*)d_in[5];
    float* out = (float*)d_out;

    // sum|D| = sum_{d=0}^{S-1} (S-d) * gamma^(-d);  D[i,j] = gamma^(j-i), i>=j
    double acc = 0.0, gp = 1.0;
    const double ginv = 1.0 / GAMMA;
    for (int d = 0; d < SS; ++d) { acc += (double)(SS - d) * gp; gp *= ginv; }
    const double scoreScale = 1.0 / (sqrt(acc) * 16.0);   // invNorm / sqrt(dim)
    const float sScale = (float)sqrt(scoreScale);         // split between Qt and Kt
    const float log2gi = (float)(-log(GAMMA) / log(2.0)); // log2(1/gamma) > 0

    proj_kernel<<<dim3(128, 4, 3), 128>>>(xq, xk, xv, Wq, Wk, Wv, sScale, log2gi);
    scores_kernel<<<dim3(136, 8), 128>>>();
    vprime_kernel<<<BB * SS, 256>>>();
    out_kernel<<<dim3(8, 4, 8), 128>>>();
    combine_kernel<<<4096, 256>>>(out);
}

// round 15
// speedup vs baseline: 1.8116x; 1.4637x over previous
#include <cuda_runtime.h>
#include <cstdint>
#include <math.h>

// Problem constants
#define BB    8
#define SS    2048
#define DIN   256
#define DIMN  256
#define GAMMA 0.9865
#define NCH   16          // chunks of 128 along sequence

// Linear-attention formulation (decay folded into Q/K):
//   Qt_i = Q_i * g^-i * s,  Kt_j = K_j * g^j * s   (s = sqrt(scoreScale))
//   denom[i] = Qt_i . cumsum(Kt)[i]  (closed form, R9-proven)
//   V' = V / max(|denom|, 1)
//   G_c = Kt_c^T V'_c   [256x256 per chunk]
//   S_c = sum_{c'<c} G_c'  (exclusive prefix)
//   out_c = Qt_c @ S_c + tril(Qt_c Kt_c^T) @ V'_c
// ---------------------------------------------------------------------------
__device__ float g_Q[BB * SS * DIMN];                 // Qt
__device__ float g_K[BB * SS * DIMN];                 // Kt
__device__ float g_V[BB * SS * DIMN];                 // V then V'
__device__ float g_KT[BB * DIMN * SS];                // Kt transposed [b][dk][s]
__device__ float g_G[BB * NCH * DIMN * DIMN];         // per-chunk outer products (33.5 MB)
__device__ float g_S[BB * NCH * DIMN * DIMN];         // exclusive prefix states (33.5 MB)
__device__ float g_diag[BB * NCH * 128 * 128];        // masked diagonal scores (8.4 MB)
__device__ float g_cumK[BB * SS * DIMN];              // inclusive prefix of Kt
__device__ float g_segsum[BB * 64 * DIMN];
__device__ float g_denom[BB * SS];

__device__ __forceinline__ float4 ld4(const float* p) {
    return *reinterpret_cast<const float4*>(p);
}
__device__ __forceinline__ void splitu(float x, uint32_t& h, uint32_t& l) {
    uint32_t u;
    asm("cvt.rna.tf32.f32 %0, %1;" : "=r"(u) : "f"(x));
    h = u;
    l = __float_as_uint(x - __uint_as_float(u));
}
__device__ __forceinline__ uint32_t to_tf32(float x) {
    uint32_t u;
    asm("cvt.rna.tf32.f32 %0, %1;" : "=r"(u) : "f"(x));
    return u;
}
__device__ __forceinline__ void mma_tf32(float* c,
                                         uint32_t a0, uint32_t a1, uint32_t a2, uint32_t a3,
                                         uint32_t b0, uint32_t b1) {
    asm volatile(
        "mma.sync.aligned.m16n8k8.row.col.f32.tf32.tf32.f32 "
        "{%0,%1,%2,%3},{%4,%5,%6,%7},{%8,%9},{%0,%1,%2,%3};\n"
        : "+f"(c[0]), "+f"(c[1]), "+f"(c[2]), "+f"(c[3])
        : "r"(a0), "r"(a1), "r"(a2), "r"(a3), "r"(b0), "r"(b1));
}

// ---------------------------------------------------------------------------
// A smem: float4 aSm[16][32], XOR-swizzled fragments.
// ---------------------------------------------------------------------------
__device__ __forceinline__ void ldgA(const float* __restrict__ g, int ld, int row0, int k0,
                                     int t, float4 st[4]) {
    int ks = t >> 6, mg = (t >> 3) & 7, r = t & 7;
    const float* p = g + (size_t)(row0 + mg * 16 + r) * ld + (k0 + ks * 8);
    st[0] = ld4(p); st[1] = ld4(p + 4);
    p += (size_t)8 * ld;
    st[2] = ld4(p); st[3] = ld4(p + 4);
}
__device__ __forceinline__ void stsA(float4* aSm, int t, const float4 st[4]) {
    int ks = t >> 6, mg = (t >> 3) & 7, r = t & 7;
    int base = (ks * 8 + mg) * 32, sw = (r >> 1) & 3, r4 = r * 4;
    aSm[base + ((r4 + 0) ^ sw)] = make_float4(st[0].x, st[2].x, st[1].x, st[3].x);
    aSm[base + ((r4 + 1) ^ sw)] = make_float4(st[0].y, st[2].y, st[1].y, st[3].y);
    aSm[base + ((r4 + 2) ^ sw)] = make_float4(st[0].z, st[2].z, st[1].z, st[3].z);
    aSm[base + ((r4 + 3) ^ sw)] = make_float4(st[0].w, st[2].w, st[1].w, st[3].w);
}

// --------------------------- B smem, 64 cols (proj) -------------------------
__device__ __forceinline__ void ldgBD(const float* __restrict__ g, int ld, int k0, int col0,
                                      int t, float4 st[2]) {
    int kq = t & 3, cg = (t >> 2) & 15, ks = t >> 6;
    const float* p = g + (size_t)(k0 + ks * 8 + kq) * ld + col0 + cg * 4;
    st[0] = ld4(p);
    st[1] = ld4(p + (size_t)4 * ld);
}
__device__ __forceinline__ void stsBD(float2* bSm, int t, const float4 st[2]) {
    int kq = t & 3, cg = (t >> 2) & 15, ks = t >> 6;
    int base = (ks * 64 + cg * 4) * 4 + (kq ^ (cg & 3));
    bSm[base + 0]  = make_float2(st[0].x, st[1].x);
    bSm[base + 4]  = make_float2(st[0].y, st[1].y);
    bSm[base + 8]  = make_float2(st[0].z, st[1].z);
    bSm[base + 12] = make_float2(st[0].w, st[1].w);
}

// --------------------------- B smem, 128 cols -------------------------------
// float2 bSm[2][128][4]: index ((ks<<7)+cc)*4 + (kq ^ ((cc>>2)&3)).
__device__ __forceinline__ void ldgBT128(const float* __restrict__ g, int ld, int row0, int k0,
                                         int t, float4 st[4]) {
#pragma unroll
    for (int uu = 0; uu < 2; ++uu) {
        int u = t + uu * 128;
        int cc = u & 127, ks = u >> 7;
        const float* p = g + (size_t)(row0 + cc) * ld + k0 + ks * 8;
        st[uu * 2 + 0] = ld4(p);
        st[uu * 2 + 1] = ld4(p + 4);
    }
}
__device__ __forceinline__ void stsBT128(float2* bSm, int t, const float4 st[4]) {
#pragma unroll
    for (int uu = 0; uu < 2; ++uu) {
        int u = t + uu * 128;
        int cc = u & 127, ks = u >> 7;
        int sw = (cc >> 2) & 3;
        int base = ((ks << 7) + cc) * 4;
        float4 lo = st[uu * 2 + 0], hi = st[uu * 2 + 1];
        bSm[base + (0 ^ sw)] = make_float2(lo.x, hi.x);
        bSm[base + (1 ^ sw)] = make_float2(lo.y, hi.y);
        bSm[base + (2 ^ sw)] = make_float2(lo.z, hi.z);
        bSm[base + (3 ^ sw)] = make_float2(lo.w, hi.w);
    }
}
__device__ __forceinline__ void ldgBD128(const float* __restrict__ g, int ld, int k0, int col0,
                                         int t, float4 st[4]) {
#pragma unroll
    for (int uu = 0; uu < 2; ++uu) {
        int u = t + uu * 128;
        int kq = u & 3, cg = (u >> 2) & 31, ks = u >> 7;
        const float* p = g + (size_t)(k0 + ks * 8 + kq) * ld + col0 + cg * 4;
        st[uu * 2 + 0] = ld4(p);
        st[uu * 2 + 1] = ld4(p + (size_t)4 * ld);
    }
}
__device__ __forceinline__ void stsBD128(float2* bSm, int t, const float4 st[4]) {
#pragma unroll
    for (int uu = 0; uu < 2; ++uu) {
        int u = t + uu * 128;
        int kq = u & 3, cg = (u >> 2) & 31, ks = u >> 7;
        int base = ((ks << 7) + cg * 4) * 4 + (kq ^ (cg & 3));
        float4 lo = st[uu * 2 + 0], hi = st[uu * 2 + 1];
        bSm[base + 0]  = make_float2(lo.x, hi.x);
        bSm[base + 4]  = make_float2(lo.y, hi.y);
        bSm[base + 8]  = make_float2(lo.z, hi.z);
        bSm[base + 12] = make_float2(lo.w, hi.w);
    }
}

// ---------------------------------------------------------------------------
// Compute chunks. 2xTF32 split: acc += Ah*Bh + Al*Bh.
// ---------------------------------------------------------------------------
__device__ __forceinline__ void computeChunk(const float4* __restrict__ aSm,
                                             const float2* __restrict__ bSm,
                                             int mBase, int nBase, int lane,
                                             float acc[4][4][4]) {
    const int sl  = lane ^ ((lane >> 3) & 3);
    const int kqc = lane & 3;
    const int cr  = lane >> 2;
    const int mg0 = mBase >> 4;
#pragma unroll
    for (int ks = 0; ks < 2; ++ks) {
        uint32_t ah[4][4], al[4][4];
#pragma unroll
        for (int mt = 0; mt < 4; ++mt) {
            float4 fa = aSm[(ks * 8 + mg0 + mt) * 32 + sl];
            splitu(fa.x, ah[mt][0], al[mt][0]);
            splitu(fa.y, ah[mt][1], al[mt][1]);
            splitu(fa.z, ah[mt][2], al[mt][2]);
            splitu(fa.w, ah[mt][3], al[mt][3]);
        }
#pragma unroll
        for (int nt = 0; nt < 4; ++nt) {
            int cc = nBase + nt * 8 + cr;
            float2 fb = bSm[(ks * 64 + cc) * 4 + (kqc ^ ((cc >> 2) & 3))];
            uint32_t bh0 = to_tf32(fb.x);
            uint32_t bh1 = to_tf32(fb.y);
#pragma unroll
            for (int mt = 0; mt < 4; ++mt) {
                mma_tf32(acc[mt][nt], ah[mt][0], ah[mt][1], ah[mt][2], ah[mt][3], bh0, bh1);
                mma_tf32(acc[mt][nt], al[mt][0], al[mt][1], al[mt][2], al[mt][3], bh0, bh1);
            }
        }
    }
}

__device__ __forceinline__ void computeChunk128(const float4* __restrict__ aSm,
                                                const float2* __restrict__ bSm,
                                                int mBase, int nBase, int lane,
                                                float acc[4][8][4]) {
    const int sl  = lane ^ ((lane >> 3) & 3);
    const int kqc = lane & 3;
    const int cr  = lane >> 2;
    const int mg0 = mBase >> 4;
#pragma unroll
    for (int ks = 0; ks < 2; ++ks) {
        uint32_t ah[4][4], al[4][4];
#pragma unroll
        for (int mt = 0; mt < 4; ++mt) {
            float4 fa = aSm[(ks * 8 + mg0 + mt) * 32 + sl];
            splitu(fa.x, ah[mt][0], al[mt][0]);
            splitu(fa.y, ah[mt][1], al[mt][1]);
            splitu(fa.z, ah[mt][2], al[mt][2]);
            splitu(fa.w, ah[mt][3], al[mt][3]);
        }
#pragma unroll
        for (int nt = 0; nt < 8; ++nt) {
            int cc = nBase + nt * 8 + cr;
            float2 fb = bSm[((ks << 7) + cc) * 4 + (kqc ^ ((cc >> 2) & 3))];
            uint32_t bh0 = to_tf32(fb.x);
            uint32_t bh1 = to_tf32(fb.y);
#pragma unroll
            for (int mt = 0; mt < 4; ++mt) {
                mma_tf32(acc[mt][nt], ah[mt][0], ah[mt][1], ah[mt][2], ah[mt][3], bh0, bh1);
                mma_tf32(acc[mt][nt], al[mt][0], al[mt][1], al[mt][2], al[mt][3], bh0, bh1);
            }
        }
    }
}

#define INIT_ACC4(acc) \
    _Pragma("unroll") for (int _a = 0; _a < 4; ++_a) \
    _Pragma("unroll") for (int _b = 0; _b < 4; ++_b) \
    _Pragma("unroll") for (int _d = 0; _d < 4; ++_d) acc[_a][_b][_d] = 0.f

#define INIT_ACC8(acc) \
    _Pragma("unroll") for (int _a = 0; _a < 4; ++_a) \
    _Pragma("unroll") for (int _b = 0; _b < 8; ++_b) \
    _Pragma("unroll") for (int _d = 0; _d < 4; ++_d) acc[_a][_b][_d] = 0.f

// ---------------------------------------------------------------------------
// Kernel 1: projections + decay folding. grid (128, 4, 3), block 128.
// ---------------------------------------------------------------------------
__global__ __launch_bounds__(128, 3)
void proj_kernel(const float* __restrict__ xq, const float* __restrict__ xk,
                 const float* __restrict__ xv,
                 const float* __restrict__ Wq, const float* __restrict__ Wk,
                 const float* __restrict__ Wv,
                 float sScale, float log2gi) {
    __shared__ float4 aSm[1024];
    __shared__ float2 bSm[1024];
    const int tid = threadIdx.x, lane = tid & 31, warp = tid >> 5;
    const int mBase = (warp >> 1) * 64, nBase = (warp & 1) * 32;
    const int row0 = blockIdx.x * 128, col0 = blockIdx.y * 64;
    const int z = blockIdx.z;

    const float* X; const float* W; float* O;
    if (z == 0)      { X = xq; W = Wq; O = g_Q; }
    else if (z == 1) { X = xk; W = Wk; O = g_K; }
    else             { X = xv; W = Wv; O = g_V; }

    float acc[4][4][4];
    INIT_ACC4(acc);
    {
        float4 stA[4], stB[2];
        ldgA(X, DIN, row0, 0, tid, stA);
        ldgBD(W, DIMN, 0, col0, tid, stB);
        stsA(aSm, tid, stA);
        stsBD(bSm, tid, stB);
        for (int c = 0; c < DIN / 16; ++c) {
            __syncthreads();
            const bool more = (c + 1) < DIN / 16;
            if (more) {
                ldgA(X, DIN, row0, (c + 1) * 16, tid, stA);
                ldgBD(W, DIMN, (c + 1) * 16, col0, tid, stB);
            }
            computeChunk(aSm + (c & 1) * 512, bSm + (c & 1) * 512, mBase, nBase, lane, acc);
            if (more) {
                stsA(aSm + ((c + 1) & 1) * 512, tid, stA);
                stsBD(bSm + ((c + 1) & 1) * 512, tid, stB);
            }
        }
    }

#pragma unroll
    for (int mt = 0; mt < 4; ++mt) {
        const int r = row0 + mBase + mt * 16 + (lane >> 2);
        float f0 = 1.f, f1 = 1.f;
        if (z == 0) {
            f0 = sScale * exp2f((float)(r & (SS - 1)) * log2gi);
            f1 = sScale * exp2f((float)((r + 8) & (SS - 1)) * log2gi);
        } else if (z == 1) {
            f0 = sScale * exp2f(-(float)(r & (SS - 1)) * log2gi);
            f1 = sScale * exp2f(-(float)((r + 8) & (SS - 1)) * log2gi);
        }
#pragma unroll
        for (int nt = 0; nt < 4; ++nt) {
            int cc = col0 + nBase + nt * 8 + (lane & 3) * 2;
            *reinterpret_cast<float2*>(O + (size_t)r * DIMN + cc) =
                make_float2(acc[mt][nt][0] * f0, acc[mt][nt][1] * f0);
            *reinterpret_cast<float2*>(O + (size_t)(r + 8) * DIMN + cc) =
                make_float2(acc[mt][nt][2] * f1, acc[mt][nt][3] * f1);
        }
    }
}

// ---------------------------------------------------------------------------
// Denominator suite (R9/R11-proven): rowsum[t] = Qt_t . cumsum(Kt)[t]
// ---------------------------------------------------------------------------
__global__ void segsum_kernel() {          // grid (64, 8), block 256
    const int seg = blockIdx.x, b = blockIdx.y, d = threadIdx.x;
    const float* p = g_K + ((size_t)b * SS + seg * 32) * DIMN + d;
    float s = 0.f;
#pragma unroll 8
    for (int k = 0; k < 32; ++k) s += p[(size_t)k * DIMN];
    g_segsum[((size_t)b * 64 + seg) * DIMN + d] = s;
}
__global__ void segpre_kernel() {          // grid 8, block 256 (exclusive prefix)
    const int b = blockIdx.x, d = threadIdx.x;
    float run = 0.f;
    for (int s = 0; s < 64; ++s) {
        const size_t idx = ((size_t)b * 64 + s) * DIMN + d;
        const float v = g_segsum[idx];
        g_segsum[idx] = run;
        run += v;
    }
}
__global__ void cumk_kernel() {            // grid (64, 8), block 256
    const int seg = blockIdx.x, b = blockIdx.y, d = threadIdx.x;
    const float* p = g_K + ((size_t)b * SS + seg * 32) * DIMN + d;
    float* o = g_cumK + ((size_t)b * SS + seg * 32) * DIMN + d;
    float run = g_segsum[((size_t)b * 64 + seg) * DIMN + d];
#pragma unroll 8
    for (int k = 0; k < 32; ++k) {
        run += p[(size_t)k * DIMN];
        o[(size_t)k * DIMN] = run;
    }
}
__global__ void denom_kernel() {           // grid 2048, block 256 (warp per row)
    const int row = blockIdx.x * 8 + (threadIdx.x >> 5);
    const int lane = threadIdx.x & 31;
    const float* q = g_Q + (size_t)row * DIMN + lane * 8;
    const float* c = g_cumK + (size_t)row * DIMN + lane * 8;
    float s = 0.f;
#pragma unroll
    for (int i = 0; i < 8; i += 4) {
        float4 a = ld4(q + i), v = ld4(c + i);
        s += a.x * v.x + a.y * v.y + a.z * v.z + a.w * v.w;
    }
#pragma unroll
    for (int o = 16; o; o >>= 1) s += __shfl_xor_sync(0xffffffffu, s, o);
    if (lane == 0) g_denom[row] = s;
}
__global__ void vprime_kernel() {          // grid BB*SS, block 256
    const int row = blockIdx.x;
    const float inv = 1.f / fmaxf(fabsf(g_denom[row]), 1.f);
    g_V[(size_t)row * DIMN + threadIdx.x] *= inv;
}

// ---------------------------------------------------------------------------
// Transpose Kt -> g_KT[b][dk][s]. grid (64, 8, 8), block (32, 8).
// ---------------------------------------------------------------------------
__global__ void ktrans_kernel() {
    __shared__ float tile[32][33];
    const int b = blockIdx.z;
    const int s0 = blockIdx.x * 32, d0 = blockIdx.y * 32;
    const float* Kp = g_K + (size_t)b * SS * DIMN;
    float* Tp = g_KT + (size_t)b * DIMN * SS;
#pragma unroll
    for (int r = 0; r < 32; r += 8)
        tile[threadIdx.y + r][threadIdx.x] =
            Kp[(size_t)(s0 + threadIdx.y + r) * DIMN + d0 + threadIdx.x];
    __syncthreads();
#pragma unroll
    for (int r = 0; r < 32; r += 8)
        Tp[(size_t)(d0 + threadIdx.y + r) * SS + s0 + threadIdx.x] =
            tile[threadIdx.x][threadIdx.y + r];
}

// ---------------------------------------------------------------------------
// Kernel G: G_c = Kt_c^T V'_c  [256x256]. grid (4, 16, 8), block 128.
// blockIdx.x: mtile = x&1 (dk), ntile = x>>1 (dv). 8 chunks of k16.
// ---------------------------------------------------------------------------
__global__ __launch_bounds__(128)
void gmat_kernel() {
    __shared__ float4 aSm[1024];
    __shared__ float2 bSm[2048];
    const int tid = threadIdx.x, lane = tid & 31, warp = tid >> 5;
    const int mBase = (warp >> 1) * 64, nBase = (warp & 1) * 64;
    const int mtile = blockIdx.x & 1, ntile = blockIdx.x >> 1;
    const int c = blockIdx.y, b = blockIdx.z;

    const float* Ap = g_KT + (size_t)b * DIMN * SS;   // [dk][s]
    const float* Vp = g_V + (size_t)b * SS * DIMN;    // [s][dv]

    float acc[4][8][4];
    INIT_ACC8(acc);
    {
        float4 stA[4], stB[4];
        ldgA(Ap, SS, mtile * 128, c * 128, tid, stA);
        ldgBD128(Vp, DIMN, c * 128, ntile * 128, tid, stB);
        stsA(aSm, tid, stA);
        stsBD128(bSm, tid, stB);
        for (int ci = 0; ci < 8; ++ci) {
            __syncthreads();
            const bool more = (ci + 1) < 8;
            if (more) {
                const int k0 = c * 128 + (ci + 1) * 16;
                ldgA(Ap, SS, mtile * 128, k0, tid, stA);
                ldgBD128(Vp, DIMN, k0, ntile * 128, tid, stB);
            }
            computeChunk128(aSm + (ci & 1) * 512, bSm + (ci & 1) * 1024, mBase, nBase, lane, acc);
            if (more) {
                stsA(aSm + ((ci + 1) & 1) * 512, tid, stA);
                stsBD128(bSm + ((ci + 1) & 1) * 1024, tid, stB);
            }
        }
    }

    float* Gp = g_G + ((size_t)(b * NCH + c)) * DIMN * DIMN;
#pragma unroll
    for (int mt = 0; mt < 4; ++mt)
#pragma unroll
        for (int nt = 0; nt < 8; ++nt) {
            int r  = mtile * 128 + mBase + mt * 16 + (lane >> 2);
            int cc = ntile * 128 + nBase + nt * 8 + (lane & 3) * 2;
            *reinterpret_cast<float2*>(Gp + (size_t)r * DIMN + cc) =
                make_float2(acc[mt][nt][0], acc[mt][nt][1]);
            *reinterpret_cast<float2*>(Gp + (size_t)(r + 8) * DIMN + cc) =
                make_float2(acc[mt][nt][2], acc[mt][nt][3]);
        }
}

// ---------------------------------------------------------------------------
// Prefix over chunks: S_c = sum_{c'<c} G_c' (exclusive). grid (128, 8), block 128.
// ---------------------------------------------------------------------------
__global__ void sprefix_kernel() {
    const int b = blockIdx.y;
    const size_t e = ((size_t)blockIdx.x * 128 + threadIdx.x) * 4;   // 0..65532
    float4 run = make_float4(0.f, 0.f, 0.f, 0.f);
    for (int c = 0; c < NCH; ++c) {
        const size_t idx = ((size_t)(b * NCH + c)) * DIMN * DIMN + e;
        *reinterpret_cast<float4*>(&g_S[idx]) = run;
        float4 gval = ld4(&g_G[idx]);
        run.x += gval.x; run.y += gval.y; run.z += gval.z; run.w += gval.w;
    }
}

// ---------------------------------------------------------------------------
// Diagonal scores: g_diag[b][c] = tril(Qt_c Kt_c^T) [128x128]. grid (16, 8).
// ---------------------------------------------------------------------------
__global__ __launch_bounds__(128)
void diag_kernel() {
    __shared__ float4 aSm[1024];
    __shared__ float2 bSm[2048];
    const int tid = threadIdx.x, lane = tid & 31, warp = tid >> 5;
    const int mBase = (warp >> 1) * 64, nBase = (warp & 1) * 64;
    const int c = blockIdx.x, b = blockIdx.y;

    const float* Qp = g_Q + (size_t)b * SS * DIMN;
    const float* Kp = g_K + (size_t)b * SS * DIMN;

    float acc[4][8][4];
    INIT_ACC8(acc);
    {
        float4 stA[4], stB[4];
        ldgA(Qp, DIMN, c * 128, 0, tid, stA);
        ldgBT128(Kp, DIMN, c * 128, 0, tid, stB);
        stsA(aSm, tid, stA);
        stsBT128(bSm, tid, stB);
        for (int ci = 0; ci < 16; ++ci) {
            __syncthreads();
            const bool more = (ci + 1) < 16;
            if (more) {
                ldgA(Qp, DIMN, c * 128, (ci + 1) * 16, tid, stA);
                ldgBT128(Kp, DIMN, c * 128, (ci + 1) * 16, tid, stB);
            }
            computeChunk128(aSm + (ci & 1) * 512, bSm + (ci & 1) * 1024, mBase, nBase, lane, acc);
            if (more) {
                stsA(aSm + ((ci + 1) & 1) * 512, tid, stA);
                stsBT128(bSm + ((ci + 1) & 1) * 1024, tid, stB);
            }
        }
    }

    float* Dp = g_diag + ((size_t)(b * NCH + c)) * 128 * 128;
#pragma unroll
    for (int mt = 0; mt < 4; ++mt)
#pragma unroll
        for (int h = 0; h < 2; ++h) {
            const int lr = mBase + mt * 16 + h * 8 + (lane >> 2);
#pragma unroll
            for (int nt = 0; nt < 8; ++nt) {
                const int colc = nBase + nt * 8 + (lane & 3) * 2;
                const int d0 = lr - colc;
                float v0 = (d0 >= 0)     ? acc[mt][nt][h * 2 + 0] : 0.f;
                float v1 = (d0 - 1 >= 0) ? acc[mt][nt][h * 2 + 1] : 0.f;
                *reinterpret_cast<float2*>(Dp + (size_t)lr * 128 + colc) = make_float2(v0, v1);
            }
        }
}

// ---------------------------------------------------------------------------
// Fused out: out_c = Qt_c @ S_c  +  diag_c @ V'_c.
// grid (16, 2, 8): x = chunk, y = col half, z = batch. 24 unified k16 chunks.
// ---------------------------------------------------------------------------
__global__ __launch_bounds__(128)
void outfused_kernel(float* __restrict__ out) {
    __shared__ float4 aSm[1024];
    __shared__ float2 bSm[2048];
    const int tid = threadIdx.x, lane = tid & 31, warp = tid >> 5;
    const int mBase = (warp >> 1) * 64, nBase = (warp & 1) * 64;
    const int c = blockIdx.x, half = blockIdx.y, b = blockIdx.z;
    const int col0 = half * 128;

    const float* Qp = g_Q + (size_t)b * SS * DIMN;
    const float* Sp = g_S + ((size_t)(b * NCH + c)) * DIMN * DIMN;   // [dk][dv]
    const float* Dp = g_diag + ((size_t)(b * NCH + c)) * 128 * 128;  // [i][s']
    const float* Vp = g_V + (size_t)b * SS * DIMN;

    auto loadChunk = [&](int ci, float4 stA[4], float4 stB[4]) {
        if (ci < 16) {
            ldgA(Qp, DIMN, c * 128, ci * 16, tid, stA);
            ldgBD128(Sp, DIMN, ci * 16, col0, tid, stB);
        } else {
            const int kk = (ci - 16) * 16;
            ldgA(Dp, 128, 0, kk, tid, stA);
            ldgBD128(Vp, DIMN, c * 128 + kk, col0, tid, stB);
        }
    };

    float acc[4][8][4];
    INIT_ACC8(acc);
    {
        float4 stA[4], stB[4];
        loadChunk(0, stA, stB);
        stsA(aSm, tid, stA);
        stsBD128(bSm, tid, stB);
        for (int ci = 0; ci < 24; ++ci) {
            __syncthreads();
            const bool more = (ci + 1) < 24;
            if (more) loadChunk(ci + 1, stA, stB);
            computeChunk128(aSm + (ci & 1) * 512, bSm + (ci & 1) * 1024, mBase, nBase, lane, acc);
            if (more) {
                stsA(aSm + ((ci + 1) & 1) * 512, tid, stA);
                stsBD128(bSm + ((ci + 1) & 1) * 1024, tid, stB);
            }
        }
    }

    float* Ob = out + (size_t)b * SS * DIMN;
#pragma unroll
    for (int mt = 0; mt < 4; ++mt)
#pragma unroll
        for (int nt = 0; nt < 8; ++nt) {
            int r  = c * 128 + mBase + mt * 16 + (lane >> 2);
            int cc = col0 + nBase + nt * 8 + (lane & 3) * 2;
            *reinterpret_cast<float2*>(Ob + (size_t)r * DIMN + cc) =
                make_float2(acc[mt][nt][0], acc[mt][nt][1]);
            *reinterpret_cast<float2*>(Ob + (size_t)(r + 8) * DIMN + cc) =
                make_float2(acc[mt][nt][2], acc[mt][nt][3]);
        }
}

// ---------------------------------------------------------------------------
// Launch
// ---------------------------------------------------------------------------
extern "C" void kernel_launch(void* const* d_in, const int* in_sizes, int n_in,
                              void* d_out, int out_size) {
    const float* xq = (const float*)d_in[0];
    const float* xk = (const float*)d_in[1];
    const float* xv = (const float*)d_in[2];
    const float* Wq = (const float*)d_in[3];
    const float* Wk = (const float*)d_in[4];
    const float* Wv = (const float*)d_in[5];
    float* out = (float*)d_out;

    // sum|D| = sum_{d=0}^{S-1} (S-d) * gamma^(-d);  D[i,j] = gamma^(j-i), i>=j
    double acc = 0.0, gp = 1.0;
    const double ginv = 1.0 / GAMMA;
    for (int d = 0; d < SS; ++d) { acc += (double)(SS - d) * gp; gp *= ginv; }
    const double scoreScale = 1.0 / (sqrt(acc) * 16.0);   // invNorm / sqrt(dim)
    const float sScale = (float)sqrt(scoreScale);         // split between Qt and Kt
    const float log2gi = (float)(-log(GAMMA) / log(2.0)); // log2(1/gamma) > 0

    proj_kernel<<<dim3(128, 4, 3), 128>>>(xq, xk, xv, Wq, Wk, Wv, sScale, log2gi);
    segsum_kernel<<<dim3(64, 8), 256>>>();
    segpre_kernel<<<8, 256>>>();
    cumk_kernel<<<dim3(64, 8), 256>>>();
    denom_kernel<<<2048, 256>>>();
    vprime_kernel<<<BB * SS, 256>>>();
    ktrans_kernel<<<dim3(64, 8, 8), dim3(32, 8)>>>();
    diag_kernel<<<dim3(16, 8), 128>>>();
    gmat_kernel<<<dim3(4, 16, 8), 128>>>();
    sprefix_kernel<<<dim3(128, 8), 128>>>();
    outfused_kernel<<<dim3(16, 2, 8), 128>>>(out);
}

// round 16
// speedup vs baseline: 1.8384x; 1.0148x over previous
#include <cuda_runtime.h>
#include <cstdint>
#include <math.h>

// Problem constants
#define BB    8
#define SS    2048
#define DIN   256
#define DIMN  256
#define GAMMA 0.9865
#define NCH   16          // chunks of 128 along sequence

// Linear-attention formulation (decay folded into Q/K):
//   Qt_i = Q_i * g^-i * s,  Kt_j = K_j * g^j * s   (s = sqrt(scoreScale))
//   diag_c = tril(Qt_c Kt_c^T)          [128x128/chunk]
//   denom[i] = rowsum(diag_c)[i] + Qt_i . ksumExcl[c]   (no cumK array!)
//   V' = V / max(|denom|, 1)
//   G_c = Kt_c^T V'_c; S_c = exclusive prefix; out_c = Qt_c@S_c + diag_c@V'_c
// ---------------------------------------------------------------------------
__device__ float g_Q[BB * SS * DIMN];                 // Qt
__device__ float g_K[BB * SS * DIMN];                 // Kt
__device__ float g_V[BB * SS * DIMN];                 // V then V'
__device__ float g_KT[BB * DIMN * SS];                // Kt transposed [b][dk][s]
__device__ float g_G[BB * NCH * DIMN * DIMN];         // per-chunk outer products
__device__ float g_S[BB * NCH * DIMN * DIMN];         // exclusive prefix states
__device__ float g_diag[BB * NCH * 128 * 128];        // masked diagonal scores
__device__ float g_segsum[BB * 64 * DIMN];            // per-32-seg K column sums
__device__ float g_ksum[BB * NCH * DIMN];             // exclusive chunk prefix of K sums
__device__ float g_dsum[BB * SS];                     // diag row sums
__device__ float g_denom[BB * SS];

__device__ __forceinline__ float4 ld4(const float* p) {
    return *reinterpret_cast<const float4*>(p);
}
__device__ __forceinline__ void splitu(float x, uint32_t& h, uint32_t& l) {
    uint32_t u;
    asm("cvt.rna.tf32.f32 %0, %1;" : "=r"(u) : "f"(x));
    h = u;
    l = __float_as_uint(x - __uint_as_float(u));
}
__device__ __forceinline__ uint32_t to_tf32(float x) {
    uint32_t u;
    asm("cvt.rna.tf32.f32 %0, %1;" : "=r"(u) : "f"(x));
    return u;
}
__device__ __forceinline__ void mma_tf32(float* c,
                                         uint32_t a0, uint32_t a1, uint32_t a2, uint32_t a3,
                                         uint32_t b0, uint32_t b1) {
    asm volatile(
        "mma.sync.aligned.m16n8k8.row.col.f32.tf32.tf32.f32 "
        "{%0,%1,%2,%3},{%4,%5,%6,%7},{%8,%9},{%0,%1,%2,%3};\n"
        : "+f"(c[0]), "+f"(c[1]), "+f"(c[2]), "+f"(c[3])
        : "r"(a0), "r"(a1), "r"(a2), "r"(a3), "r"(b0), "r"(b1));
}

// ---------------------------------------------------------------------------
// A smem: float4 aSm[16][32], XOR-swizzled fragments.
// ---------------------------------------------------------------------------
__device__ __forceinline__ void ldgA(const float* __restrict__ g, int ld, int row0, int k0,
                                     int t, float4 st[4]) {
    int ks = t >> 6, mg = (t >> 3) & 7, r = t & 7;
    const float* p = g + (size_t)(row0 + mg * 16 + r) * ld + (k0 + ks * 8);
    st[0] = ld4(p); st[1] = ld4(p + 4);
    p += (size_t)8 * ld;
    st[2] = ld4(p); st[3] = ld4(p + 4);
}
__device__ __forceinline__ void stsA(float4* aSm, int t, const float4 st[4]) {
    int ks = t >> 6, mg = (t >> 3) & 7, r = t & 7;
    int base = (ks * 8 + mg) * 32, sw = (r >> 1) & 3, r4 = r * 4;
    aSm[base + ((r4 + 0) ^ sw)] = make_float4(st[0].x, st[2].x, st[1].x, st[3].x);
    aSm[base + ((r4 + 1) ^ sw)] = make_float4(st[0].y, st[2].y, st[1].y, st[3].y);
    aSm[base + ((r4 + 2) ^ sw)] = make_float4(st[0].z, st[2].z, st[1].z, st[3].z);
    aSm[base + ((r4 + 3) ^ sw)] = make_float4(st[0].w, st[2].w, st[1].w, st[3].w);
}

// --------------------------- B smem, 64 cols (proj) -------------------------
__device__ __forceinline__ void ldgBD(const float* __restrict__ g, int ld, int k0, int col0,
                                      int t, float4 st[2]) {
    int kq = t & 3, cg = (t >> 2) & 15, ks = t >> 6;
    const float* p = g + (size_t)(k0 + ks * 8 + kq) * ld + col0 + cg * 4;
    st[0] = ld4(p);
    st[1] = ld4(p + (size_t)4 * ld);
}
__device__ __forceinline__ void stsBD(float2* bSm, int t, const float4 st[2]) {
    int kq = t & 3, cg = (t >> 2) & 15, ks = t >> 6;
    int base = (ks * 64 + cg * 4) * 4 + (kq ^ (cg & 3));
    bSm[base + 0]  = make_float2(st[0].x, st[1].x);
    bSm[base + 4]  = make_float2(st[0].y, st[1].y);
    bSm[base + 8]  = make_float2(st[0].z, st[1].z);
    bSm[base + 12] = make_float2(st[0].w, st[1].w);
}

// --------------------------- B smem, 128 cols -------------------------------
__device__ __forceinline__ void ldgBT128(const float* __restrict__ g, int ld, int row0, int k0,
                                         int t, float4 st[4]) {
#pragma unroll
    for (int uu = 0; uu < 2; ++uu) {
        int u = t + uu * 128;
        int cc = u & 127, ks = u >> 7;
        const float* p = g + (size_t)(row0 + cc) * ld + k0 + ks * 8;
        st[uu * 2 + 0] = ld4(p);
        st[uu * 2 + 1] = ld4(p + 4);
    }
}
__device__ __forceinline__ void stsBT128(float2* bSm, int t, const float4 st[4]) {
#pragma unroll
    for (int uu = 0; uu < 2; ++uu) {
        int u = t + uu * 128;
        int cc = u & 127, ks = u >> 7;
        int sw = (cc >> 2) & 3;
        int base = ((ks << 7) + cc) * 4;
        float4 lo = st[uu * 2 + 0], hi = st[uu * 2 + 1];
        bSm[base + (0 ^ sw)] = make_float2(lo.x, hi.x);
        bSm[base + (1 ^ sw)] = make_float2(lo.y, hi.y);
        bSm[base + (2 ^ sw)] = make_float2(lo.z, hi.z);
        bSm[base + (3 ^ sw)] = make_float2(lo.w, hi.w);
    }
}
__device__ __forceinline__ void ldgBD128(const float* __restrict__ g, int ld, int k0, int col0,
                                         int t, float4 st[4]) {
#pragma unroll
    for (int uu = 0; uu < 2; ++uu) {
        int u = t + uu * 128;
        int kq = u & 3, cg = (u >> 2) & 31, ks = u >> 7;
        const float* p = g + (size_t)(k0 + ks * 8 + kq) * ld + col0 + cg * 4;
        st[uu * 2 + 0] = ld4(p);
        st[uu * 2 + 1] = ld4(p + (size_t)4 * ld);
    }
}
__device__ __forceinline__ void stsBD128(float2* bSm, int t, const float4 st[4]) {
#pragma unroll
    for (int uu = 0; uu < 2; ++uu) {
        int u = t + uu * 128;
        int kq = u & 3, cg = (u >> 2) & 31, ks = u >> 7;
        int base = ((ks << 7) + cg * 4) * 4 + (kq ^ (cg & 3));
        float4 lo = st[uu * 2 + 0], hi = st[uu * 2 + 1];
        bSm[base + 0]  = make_float2(lo.x, hi.x);
        bSm[base + 4]  = make_float2(lo.y, hi.y);
        bSm[base + 8]  = make_float2(lo.z, hi.z);
        bSm[base + 12] = make_float2(lo.w, hi.w);
    }
}

// ---------------------------------------------------------------------------
// Compute chunks. 2xTF32 split: acc += Ah*Bh + Al*Bh.
// ---------------------------------------------------------------------------
__device__ __forceinline__ void computeChunk(const float4* __restrict__ aSm,
                                             const float2* __restrict__ bSm,
                                             int mBase, int nBase, int lane,
                                             float acc[4][4][4]) {
    const int sl  = lane ^ ((lane >> 3) & 3);
    const int kqc = lane & 3;
    const int cr  = lane >> 2;
    const int mg0 = mBase >> 4;
#pragma unroll
    for (int ks = 0; ks < 2; ++ks) {
        uint32_t ah[4][4], al[4][4];
#pragma unroll
        for (int mt = 0; mt < 4; ++mt) {
            float4 fa = aSm[(ks * 8 + mg0 + mt) * 32 + sl];
            splitu(fa.x, ah[mt][0], al[mt][0]);
            splitu(fa.y, ah[mt][1], al[mt][1]);
            splitu(fa.z, ah[mt][2], al[mt][2]);
            splitu(fa.w, ah[mt][3], al[mt][3]);
        }
#pragma unroll
        for (int nt = 0; nt < 4; ++nt) {
            int cc = nBase + nt * 8 + cr;
            float2 fb = bSm[(ks * 64 + cc) * 4 + (kqc ^ ((cc >> 2) & 3))];
            uint32_t bh0 = to_tf32(fb.x);
            uint32_t bh1 = to_tf32(fb.y);
#pragma unroll
            for (int mt = 0; mt < 4; ++mt) {
                mma_tf32(acc[mt][nt], ah[mt][0], ah[mt][1], ah[mt][2], ah[mt][3], bh0, bh1);
                mma_tf32(acc[mt][nt], al[mt][0], al[mt][1], al[mt][2], al[mt][3], bh0, bh1);
            }
        }
    }
}

__device__ __forceinline__ void computeChunk128(const float4* __restrict__ aSm,
                                                const float2* __restrict__ bSm,
                                                int mBase, int nBase, int lane,
                                                float acc[4][8][4]) {
    const int sl  = lane ^ ((lane >> 3) & 3);
    const int kqc = lane & 3;
    const int cr  = lane >> 2;
    const int mg0 = mBase >> 4;
#pragma unroll
    for (int ks = 0; ks < 2; ++ks) {
        uint32_t ah[4][4], al[4][4];
#pragma unroll
        for (int mt = 0; mt < 4; ++mt) {
            float4 fa = aSm[(ks * 8 + mg0 + mt) * 32 + sl];
            splitu(fa.x, ah[mt][0], al[mt][0]);
            splitu(fa.y, ah[mt][1], al[mt][1]);
            splitu(fa.z, ah[mt][2], al[mt][2]);
            splitu(fa.w, ah[mt][3], al[mt][3]);
        }
#pragma unroll
        for (int nt = 0; nt < 8; ++nt) {
            int cc = nBase + nt * 8 + cr;
            float2 fb = bSm[((ks << 7) + cc) * 4 + (kqc ^ ((cc >> 2) & 3))];
            uint32_t bh0 = to_tf32(fb.x);
            uint32_t bh1 = to_tf32(fb.y);
#pragma unroll
            for (int mt = 0; mt < 4; ++mt) {
                mma_tf32(acc[mt][nt], ah[mt][0], ah[mt][1], ah[mt][2], ah[mt][3], bh0, bh1);
                mma_tf32(acc[mt][nt], al[mt][0], al[mt][1], al[mt][2], al[mt][3], bh0, bh1);
            }
        }
    }
}

#define INIT_ACC4(acc) \
    _Pragma("unroll") for (int _a = 0; _a < 4; ++_a) \
    _Pragma("unroll") for (int _b = 0; _b < 4; ++_b) \
    _Pragma("unroll") for (int _d = 0; _d < 4; ++_d) acc[_a][_b][_d] = 0.f

#define INIT_ACC8(acc) \
    _Pragma("unroll") for (int _a = 0; _a < 4; ++_a) \
    _Pragma("unroll") for (int _b = 0; _b < 8; ++_b) \
    _Pragma("unroll") for (int _d = 0; _d < 4; ++_d) acc[_a][_b][_d] = 0.f

// ---------------------------------------------------------------------------
// Kernel 1: projections + decay folding. grid (128, 4, 3), block 128.
// ---------------------------------------------------------------------------
__global__ __launch_bounds__(128, 3)
void proj_kernel(const float* __restrict__ xq, const float* __restrict__ xk,
                 const float* __restrict__ xv,
                 const float* __restrict__ Wq, const float* __restrict__ Wk,
                 const float* __restrict__ Wv,
                 float sScale, float log2gi) {
    __shared__ float4 aSm[1024];
    __shared__ float2 bSm[1024];
    const int tid = threadIdx.x, lane = tid & 31, warp = tid >> 5;
    const int mBase = (warp >> 1) * 64, nBase = (warp & 1) * 32;
    const int row0 = blockIdx.x * 128, col0 = blockIdx.y * 64;
    const int z = blockIdx.z;

    const float* X; const float* W; float* O;
    if (z == 0)      { X = xq; W = Wq; O = g_Q; }
    else if (z == 1) { X = xk; W = Wk; O = g_K; }
    else             { X = xv; W = Wv; O = g_V; }

    float acc[4][4][4];
    INIT_ACC4(acc);
    {
        float4 stA[4], stB[2];
        ldgA(X, DIN, row0, 0, tid, stA);
        ldgBD(W, DIMN, 0, col0, tid, stB);
        stsA(aSm, tid, stA);
        stsBD(bSm, tid, stB);
        for (int c = 0; c < DIN / 16; ++c) {
            __syncthreads();
            const bool more = (c + 1) < DIN / 16;
            if (more) {
                ldgA(X, DIN, row0, (c + 1) * 16, tid, stA);
                ldgBD(W, DIMN, (c + 1) * 16, col0, tid, stB);
            }
            computeChunk(aSm + (c & 1) * 512, bSm + (c & 1) * 512, mBase, nBase, lane, acc);
            if (more) {
                stsA(aSm + ((c + 1) & 1) * 512, tid, stA);
                stsBD(bSm + ((c + 1) & 1) * 512, tid, stB);
            }
        }
    }

#pragma unroll
    for (int mt = 0; mt < 4; ++mt) {
        const int r = row0 + mBase + mt * 16 + (lane >> 2);
        float f0 = 1.f, f1 = 1.f;
        if (z == 0) {
            f0 = sScale * exp2f((float)(r & (SS - 1)) * log2gi);
            f1 = sScale * exp2f((float)((r + 8) & (SS - 1)) * log2gi);
        } else if (z == 1) {
            f0 = sScale * exp2f(-(float)(r & (SS - 1)) * log2gi);
            f1 = sScale * exp2f(-(float)((r + 8) & (SS - 1)) * log2gi);
        }
#pragma unroll
        for (int nt = 0; nt < 4; ++nt) {
            int cc = col0 + nBase + nt * 8 + (lane & 3) * 2;
            *reinterpret_cast<float2*>(O + (size_t)r * DIMN + cc) =
                make_float2(acc[mt][nt][0] * f0, acc[mt][nt][1] * f0);
            *reinterpret_cast<float2*>(O + (size_t)(r + 8) * DIMN + cc) =
                make_float2(acc[mt][nt][2] * f1, acc[mt][nt][3] * f1);
        }
    }
}

// ---------------------------------------------------------------------------
// segsum: per-32-row-segment column sums of Kt. grid (64, 8), block 256.
// ---------------------------------------------------------------------------
__global__ void segsum_kernel() {
    const int seg = blockIdx.x, b = blockIdx.y, d = threadIdx.x;
    const float* p = g_K + ((size_t)b * SS + seg * 32) * DIMN + d;
    float s = 0.f;
#pragma unroll 8
    for (int k = 0; k < 32; ++k) s += p[(size_t)k * DIMN];
    g_segsum[((size_t)b * 64 + seg) * DIMN + d] = s;
}

// kpre: exclusive chunk prefix of K sums (chunk = 4 segments). grid 8, block 256.
__global__ void kpre_kernel() {
    const int b = blockIdx.x, d = threadIdx.x;
    float run = 0.f;
    for (int c = 0; c < NCH; ++c) {
        g_ksum[((size_t)b * NCH + c) * DIMN + d] = run;
        const float* sp = g_segsum + ((size_t)b * 64 + c * 4) * DIMN + d;
        run += sp[0] + sp[(size_t)DIMN] + sp[(size_t)2 * DIMN] + sp[(size_t)3 * DIMN];
    }
}

// ---------------------------------------------------------------------------
// diag: g_diag[b][c] = tril(Qt_c Kt_c^T), ALSO emits row sums -> g_dsum.
// grid (16, 8), block 128.
// ---------------------------------------------------------------------------
__global__ __launch_bounds__(128)
void diag_kernel() {
    __shared__ float4 aSm[1024];
    __shared__ float2 bSm[2048];
    __shared__ float rowAcc[128];
    const int tid = threadIdx.x, lane = tid & 31, warp = tid >> 5;
    const int mBase = (warp >> 1) * 64, nBase = (warp & 1) * 64;
    const int c = blockIdx.x, b = blockIdx.y;

    const float* Qp = g_Q + (size_t)b * SS * DIMN;
    const float* Kp = g_K + (size_t)b * SS * DIMN;

    rowAcc[tid] = 0.f;

    float acc[4][8][4];
    INIT_ACC8(acc);
    {
        float4 stA[4], stB[4];
        ldgA(Qp, DIMN, c * 128, 0, tid, stA);
        ldgBT128(Kp, DIMN, c * 128, 0, tid, stB);
        stsA(aSm, tid, stA);
        stsBT128(bSm, tid, stB);
        for (int ci = 0; ci < 16; ++ci) {
            __syncthreads();
            const bool more = (ci + 1) < 16;
            if (more) {
                ldgA(Qp, DIMN, c * 128, (ci + 1) * 16, tid, stA);
                ldgBT128(Kp, DIMN, c * 128, (ci + 1) * 16, tid, stB);
            }
            computeChunk128(aSm + (ci & 1) * 512, bSm + (ci & 1) * 1024, mBase, nBase, lane, acc);
            if (more) {
                stsA(aSm + ((ci + 1) & 1) * 512, tid, stA);
                stsBT128(bSm + ((ci + 1) & 1) * 1024, tid, stB);
            }
        }
    }

    float* Dp = g_diag + ((size_t)(b * NCH + c)) * 128 * 128;
#pragma unroll
    for (int mt = 0; mt < 4; ++mt)
#pragma unroll
        for (int h = 0; h < 2; ++h) {
            const int lr = mBase + mt * 16 + h * 8 + (lane >> 2);
            float rsum = 0.f;
#pragma unroll
            for (int nt = 0; nt < 8; ++nt) {
                const int colc = nBase + nt * 8 + (lane & 3) * 2;
                const int d0 = lr - colc;
                float v0 = (d0 >= 0)     ? acc[mt][nt][h * 2 + 0] : 0.f;
                float v1 = (d0 - 1 >= 0) ? acc[mt][nt][h * 2 + 1] : 0.f;
                *reinterpret_cast<float2*>(Dp + (size_t)lr * 128 + colc) = make_float2(v0, v1);
                rsum += v0 + v1;
            }
            rsum += __shfl_xor_sync(0xffffffffu, rsum, 1);
            rsum += __shfl_xor_sync(0xffffffffu, rsum, 2);
            if ((lane & 3) == 0) atomicAdd(&rowAcc[lr], rsum);  // 2 commutative adds/slot
        }
    __syncthreads();
    g_dsum[(size_t)b * SS + c * 128 + tid] = rowAcc[tid];
}

// ---------------------------------------------------------------------------
// denom2: denom[i] = dsum[i] + Qt_i . ksumExcl[chunk(i)]. grid 2048, block 256.
// ---------------------------------------------------------------------------
__global__ void denom2_kernel() {
    const int row = blockIdx.x * 8 + (threadIdx.x >> 5);   // 0..16383 (b*SS + s)
    const int lane = threadIdx.x & 31;
    const int b = row >> 11, s = row & (SS - 1);
    const int c = s >> 7;
    const float* q = g_Q + (size_t)row * DIMN + lane * 8;
    const float* kp = g_ksum + ((size_t)b * NCH + c) * DIMN + lane * 8;
    float sum = 0.f;
#pragma unroll
    for (int i = 0; i < 8; i += 4) {
        float4 a = ld4(q + i), v = ld4(kp + i);
        sum += a.x * v.x + a.y * v.y + a.z * v.z + a.w * v.w;
    }
#pragma unroll
    for (int o = 16; o; o >>= 1) sum += __shfl_xor_sync(0xffffffffu, sum, o);
    if (lane == 0) g_denom[row] = sum + g_dsum[row];
}

__global__ void vprime_kernel() {          // grid BB*SS, block 256
    const int row = blockIdx.x;
    const float inv = 1.f / fmaxf(fabsf(g_denom[row]), 1.f);
    g_V[(size_t)row * DIMN + threadIdx.x] *= inv;
}

// ---------------------------------------------------------------------------
// Transpose Kt -> g_KT[b][dk][s]. grid (64, 8, 8), block (32, 8).
// ---------------------------------------------------------------------------
__global__ void ktrans_kernel() {
    __shared__ float tile[32][33];
    const int b = blockIdx.z;
    const int s0 = blockIdx.x * 32, d0 = blockIdx.y * 32;
    const float* Kp = g_K + (size_t)b * SS * DIMN;
    float* Tp = g_KT + (size_t)b * DIMN * SS;
#pragma unroll
    for (int r = 0; r < 32; r += 8)
        tile[threadIdx.y + r][threadIdx.x] =
            Kp[(size_t)(s0 + threadIdx.y + r) * DIMN + d0 + threadIdx.x];
    __syncthreads();
#pragma unroll
    for (int r = 0; r < 32; r += 8)
        Tp[(size_t)(d0 + threadIdx.y + r) * SS + s0 + threadIdx.x] =
            tile[threadIdx.x][threadIdx.y + r];
}

// ---------------------------------------------------------------------------
// gmat: G_c = Kt_c^T V'_c  [256x256]. grid (4, 16, 8), block 128.
// ---------------------------------------------------------------------------
__global__ __launch_bounds__(128)
void gmat_kernel() {
    __shared__ float4 aSm[1024];
    __shared__ float2 bSm[2048];
    const int tid = threadIdx.x, lane = tid & 31, warp = tid >> 5;
    const int mBase = (warp >> 1) * 64, nBase = (warp & 1) * 64;
    const int mtile = blockIdx.x & 1, ntile = blockIdx.x >> 1;
    const int c = blockIdx.y, b = blockIdx.z;

    const float* Ap = g_KT + (size_t)b * DIMN * SS;   // [dk][s]
    const float* Vp = g_V + (size_t)b * SS * DIMN;    // [s][dv]

    float acc[4][8][4];
    INIT_ACC8(acc);
    {
        float4 stA[4], stB[4];
        ldgA(Ap, SS, mtile * 128, c * 128, tid, stA);
        ldgBD128(Vp, DIMN, c * 128, ntile * 128, tid, stB);
        stsA(aSm, tid, stA);
        stsBD128(bSm, tid, stB);
        for (int ci = 0; ci < 8; ++ci) {
            __syncthreads();
            const bool more = (ci + 1) < 8;
            if (more) {
                const int k0 = c * 128 + (ci + 1) * 16;
                ldgA(Ap, SS, mtile * 128, k0, tid, stA);
                ldgBD128(Vp, DIMN, k0, ntile * 128, tid, stB);
            }
            computeChunk128(aSm + (ci & 1) * 512, bSm + (ci & 1) * 1024, mBase, nBase, lane, acc);
            if (more) {
                stsA(aSm + ((ci + 1) & 1) * 512, tid, stA);
                stsBD128(bSm + ((ci + 1) & 1) * 1024, tid, stB);
            }
        }
    }

    float* Gp = g_G + ((size_t)(b * NCH + c)) * DIMN * DIMN;
#pragma unroll
    for (int mt = 0; mt < 4; ++mt)
#pragma unroll
        for (int nt = 0; nt < 8; ++nt) {
            int r  = mtile * 128 + mBase + mt * 16 + (lane >> 2);
            int cc = ntile * 128 + nBase + nt * 8 + (lane & 3) * 2;
            *reinterpret_cast<float2*>(Gp + (size_t)r * DIMN + cc) =
                make_float2(acc[mt][nt][0], acc[mt][nt][1]);
            *reinterpret_cast<float2*>(Gp + (size_t)(r + 8) * DIMN + cc) =
                make_float2(acc[mt][nt][2], acc[mt][nt][3]);
        }
}

// ---------------------------------------------------------------------------
// sprefix: S_c = sum_{c'<c} G_c' (exclusive). grid (128, 8), block 128.
// ---------------------------------------------------------------------------
__global__ void sprefix_kernel() {
    const int b = blockIdx.y;
    const size_t e = ((size_t)blockIdx.x * 128 + threadIdx.x) * 4;
    float4 run = make_float4(0.f, 0.f, 0.f, 0.f);
    for (int c = 0; c < NCH; ++c) {
        const size_t idx = ((size_t)(b * NCH + c)) * DIMN * DIMN + e;
        *reinterpret_cast<float4*>(&g_S[idx]) = run;
        float4 gval = ld4(&g_G[idx]);
        run.x += gval.x; run.y += gval.y; run.z += gval.z; run.w += gval.w;
    }
}

// ---------------------------------------------------------------------------
// Fused out: out_c = Qt_c @ S_c  +  diag_c @ V'_c. grid (16, 2, 8), block 128.
// ---------------------------------------------------------------------------
__global__ __launch_bounds__(128)
void outfused_kernel(float* __restrict__ out) {
    __shared__ float4 aSm[1024];
    __shared__ float2 bSm[2048];
    const int tid = threadIdx.x, lane = tid & 31, warp = tid >> 5;
    const int mBase = (warp >> 1) * 64, nBase = (warp & 1) * 64;
    const int c = blockIdx.x, half = blockIdx.y, b = blockIdx.z;
    const int col0 = half * 128;

    const float* Qp = g_Q + (size_t)b * SS * DIMN;
    const float* Sp = g_S + ((size_t)(b * NCH + c)) * DIMN * DIMN;
    const float* Dp = g_diag + ((size_t)(b * NCH + c)) * 128 * 128;
    const float* Vp = g_V + (size_t)b * SS * DIMN;

    auto loadChunk = [&](int ci, float4 stA[4], float4 stB[4]) {
        if (ci < 16) {
            ldgA(Qp, DIMN, c * 128, ci * 16, tid, stA);
            ldgBD128(Sp, DIMN, ci * 16, col0, tid, stB);
        } else {
            const int kk = (ci - 16) * 16;
            ldgA(Dp, 128, 0, kk, tid, stA);
            ldgBD128(Vp, DIMN, c * 128 + kk, col0, tid, stB);
        }
    };

    float acc[4][8][4];
    INIT_ACC8(acc);
    {
        float4 stA[4], stB[4];
        loadChunk(0, stA, stB);
        stsA(aSm, tid, stA);
        stsBD128(bSm, tid, stB);
        for (int ci = 0; ci < 24; ++ci) {
            __syncthreads();
            const bool more = (ci + 1) < 24;
            if (more) loadChunk(ci + 1, stA, stB);
            computeChunk128(aSm + (ci & 1) * 512, bSm + (ci & 1) * 1024, mBase, nBase, lane, acc);
            if (more) {
                stsA(aSm + ((ci + 1) & 1) * 512, tid, stA);
                stsBD128(bSm + ((ci + 1) & 1) * 1024, tid, stB);
            }
        }
    }

    float* Ob = out + (size_t)b * SS * DIMN;
#pragma unroll
    for (int mt = 0; mt < 4; ++mt)
#pragma unroll
        for (int nt = 0; nt < 8; ++nt) {
            int r  = c * 128 + mBase + mt * 16 + (lane >> 2);
            int cc = col0 + nBase + nt * 8 + (lane & 3) * 2;
            *reinterpret_cast<float2*>(Ob + (size_t)r * DIMN + cc) =
                make_float2(acc[mt][nt][0], acc[mt][nt][1]);
            *reinterpret_cast<float2*>(Ob + (size_t)(r + 8) * DIMN + cc) =
                make_float2(acc[mt][nt][2], acc[mt][nt][3]);
        }
}

// ---------------------------------------------------------------------------
// Launch
// ---------------------------------------------------------------------------
extern "C" void kernel_launch(void* const* d_in, const int* in_sizes, int n_in,
                              void* d_out, int out_size) {
    const float* xq = (const float*)d_in[0];
    const float* xk = (const float*)d_in[1];
    const float* xv = (const float*)d_in[2];
    const float* Wq = (const float*)d_in[3];
    const float* Wk = (const float*)d_in[4];
    const float* Wv = (const float*)d_in[5];
    float* out = (float*)d_out;

    double acc = 0.0, gp = 1.0;
    const double ginv = 1.0 / GAMMA;
    for (int d = 0; d < SS; ++d) { acc += (double)(SS - d) * gp; gp *= ginv; }
    const double scoreScale = 1.0 / (sqrt(acc) * 16.0);
    const float sScale = (float)sqrt(scoreScale);
    const float log2gi = (float)(-log(GAMMA) / log(2.0));

    proj_kernel<<<dim3(128, 4, 3), 128>>>(xq, xk, xv, Wq, Wk, Wv, sScale, log2gi);
    segsum_kernel<<<dim3(64, 8), 256>>>();
    kpre_kernel<<<8, 256>>>();
    diag_kernel<<<dim3(16, 8), 128>>>();
    denom2_kernel<<<2048, 256>>>();
    vprime_kernel<<<BB * SS, 256>>>();
    ktrans_kernel<<<dim3(64, 8, 8), dim3(32, 8)>>>();
    gmat_kernel<<<dim3(4, 16, 8), 128>>>();
    sprefix_kernel<<<dim3(128, 8), 128>>>();
    outfused_kernel<<<dim3(16, 2, 8), 128>>>(out);
}